// round 3
// baseline (speedup 1.0000x reference)
#include <cuda_runtime.h>
#include <math.h>

#define Hc   1024
#define Nst  64
#define Lt   4096
#define OUTc 512
#define BSz  2
#define CH3  342   // per-axis posenc channels

typedef unsigned long long u64;

// ---------------- f32x2 packed math (sm_103a FFMA2 path) ----------------
__device__ __forceinline__ u64 f2fma(u64 a, u64 b, u64 c) {
    u64 d; asm("fma.rn.f32x2 %0,%1,%2,%3;" : "=l"(d) : "l"(a), "l"(b), "l"(c)); return d;
}
__device__ __forceinline__ u64 f2mul(u64 a, u64 b) {
    u64 d; asm("mul.rn.f32x2 %0,%1,%2;" : "=l"(d) : "l"(a), "l"(b)); return d;
}
__device__ __forceinline__ u64 f2add(u64 a, u64 b) {
    u64 d; asm("add.rn.f32x2 %0,%1,%2;" : "=l"(d) : "l"(a), "l"(b)); return d;
}
__device__ __forceinline__ u64 f2pack(float lo, float hi) {
    u64 d; asm("mov.b64 %0,{%1,%2};" : "=l"(d) : "f"(lo), "f"(hi)); return d;
}
__device__ __forceinline__ float2 f2unpack(u64 v) {
    float2 r; asm("mov.b64 {%0,%1},%2;" : "=f"(r.x), "=f"(r.y) : "l"(v)); return r;
}

// ---------------- scratch ----------------
__device__ float2 g_v2[BSz*Hc*Lt];    // v duplicated {v,v}, layout (b, c, l)
__device__ float  g_yT[BSz*Hc*Lt];    // gelu(conv + D*v), layout (b, c, l)
__device__ float g_wre[Hc*Nst],  g_wim[Hc*Nst];
__device__ float g_w2re[Hc*Nst], g_w2im[Hc*Nst];
__device__ float g_ctre[Hc*Nst], g_ctim[Hc*Nst];
__device__ float g_emb[3*16*CH3];     // [axis][pos][k]

// ---------------- posenc tables ----------------
__global__ void prep_emb_kernel() {
    int idx = blockIdx.x * blockDim.x + threadIdx.x;
    if (idx >= 3*16*CH3) return;
    int k   = idx % CH3;
    int pos = (idx / CH3) % 16;
    int i   = k >> 1;
    float freq = expf(-logf(10000.0f) * (float)(2*i) / (float)CH3);
    float arg  = (float)pos * freq;
    g_emb[idx] = (k & 1) ? cosf(arg) : sinf(arg);
}

// ---------------- discretize: w = exp(dt*A), Ct' = 2*C*(w-1)/A, w2 = w*w ----------------
__global__ void prep_ct_kernel(const float* __restrict__ log_dt,
                               const float* __restrict__ Are, const float* __restrict__ Aim,
                               const float* __restrict__ Cre, const float* __restrict__ Cim) {
    int idx = blockIdx.x * blockDim.x + threadIdx.x;
    if (idx >= Hc*Nst) return;
    int c = idx >> 6;
    float dt  = expf(log_dt[c]);
    float ar  = Are[idx], ai = Aim[idx];
    float dar = dt*ar, dai = dt*ai;
    float er  = expf(dar);
    float sn, cs; sincosf(dai, &sn, &cs);
    float wr = er*cs, wi = er*sn;
    g_wre[idx]  = wr; g_wim[idx]  = wi;
    g_w2re[idx] = wr*wr - wi*wi;
    g_w2im[idx] = 2.0f*wr*wi;
    float nr = wr - 1.0f, ni = wi;
    float inv = 1.0f / (ar*ar + ai*ai);
    float qr = (nr*ar + ni*ai) * inv;
    float qi = (ni*ar - nr*ai) * inv;
    float cr = Cre[idx], ci = Cim[idx];
    g_ctre[idx] = 2.0f*(cr*qr - ci*qi);
    g_ctim[idx] = 2.0f*(cr*qi + ci*qr);
}

// ---------------- v = x + posenc (duplicated store) ----------------
__global__ void v_kernel(const float* __restrict__ x) {
    int i4 = blockIdx.x * blockDim.x + threadIdx.x;
    if (i4 >= BSz*Hc*Lt/4) return;
    int l4 = i4 & (Lt/4 - 1);
    int c  = (i4 >> 10) & (Hc - 1);
    int l  = l4 << 2;
    int lw = l & 15, lh = (l >> 4) & 15, lf = l >> 8;
    float4 xv = ((const float4*)x)[i4];
    float4 pv;
    if (c < CH3) {
        float e = g_emb[lf*CH3 + c];
        pv = make_float4(e, e, e, e);
    } else if (c < 2*CH3) {
        float e = g_emb[(16 + lh)*CH3 + (c - CH3)];
        pv = make_float4(e, e, e, e);
    } else {
        int k = c - 2*CH3;
        const float* ez = g_emb + 32*CH3 + k;
        pv = make_float4(ez[(lw+0)*CH3], ez[(lw+1)*CH3], ez[(lw+2)*CH3], ez[(lw+3)*CH3]);
    }
    float v0 = xv.x+pv.x, v1 = xv.y+pv.y, v2 = xv.z+pv.z, v3 = xv.w+pv.w;
    float4* dst = (float4*)g_v2;
    dst[i4*2]   = make_float4(v0, v0, v1, v1);
    dst[i4*2+1] = make_float4(v2, v2, v3, v3);
}

// ---------------- diagonal SSM recurrence (decimated by 2) + skip + gelu ----------------
// one warp per (b, c); lane owns packed states {n=lane, n=lane+32} as f32x2
#define RPAD 68   // words per reduce row (32 float2 = 64 words + 4 pad)

__global__ __launch_bounds__(32) void ssm_kernel(const float* __restrict__ D) {
    __shared__ float ps[32*RPAD];
    int wid  = blockIdx.x;          // b*Hc + c
    int lane = threadIdx.x;
    int c    = wid & (Hc - 1);
    int n0   = (c << 6) + lane;

    u64 Wr   = f2pack( g_wre[n0],   g_wre[n0+32]);
    u64 Wi   = f2pack( g_wim[n0],   g_wim[n0+32]);
    u64 Win  = f2pack(-g_wim[n0],  -g_wim[n0+32]);
    u64 W2r  = f2pack( g_w2re[n0],  g_w2re[n0+32]);
    u64 W2i  = f2pack( g_w2im[n0],  g_w2im[n0+32]);
    u64 W2in = f2pack(-g_w2im[n0], -g_w2im[n0+32]);
    u64 Cr   = f2pack( g_ctre[n0],  g_ctre[n0+32]);
    u64 Cin  = f2pack(-g_ctim[n0], -g_ctim[n0+32]);
    float dc = D[c];

    const ulonglong2* vp = (const ulonglong2*)(g_v2 + (size_t)wid * Lt);
    const float2*     vs = g_v2 + (size_t)wid * Lt;
    float*            yp = g_yT + (size_t)wid * Lt;

    u64 Sr = 0ull, Si = 0ull, vprev = 0ull;

    for (int base = 0; base < Lt; base += 32) {
        #pragma unroll
        for (int h = 0; h < 2; ++h) {
            ulonglong2 va[8];
            #pragma unroll
            for (int q = 0; q < 8; ++q) va[q] = vp[((base + 16*h) >> 1) + q];
            #pragma unroll
            for (int q = 0; q < 8; ++q) {
                // even step: s = w2*s + (w*vprev + v0)
                u64 ir  = f2fma(Wr,  vprev, va[q].x);
                u64 ii  = f2mul(Wi,  vprev);
                u64 tr  = f2fma(W2in, Si, ir);
                u64 nSr = f2fma(W2r,  Sr, tr);
                u64 ti  = f2fma(W2r,  Si, ii);
                u64 nSi = f2fma(W2i,  Sr, ti);
                Sr = nSr; Si = nSi;
                // odd derived: so = w*s + v1  (off critical path)
                u64 orr = f2fma(Win, Si, va[q].y);
                u64 sor = f2fma(Wr,  Sr, orr);
                u64 oi  = f2mul(Wr,  Si);
                u64 soi = f2fma(Wi,  Sr, oi);
                // dots: cr*sr - ci*si
                u64 p0 = f2fma(Cin, Si,  f2mul(Cr, Sr));
                u64 p1 = f2fma(Cin, soi, f2mul(Cr, sor));
                int row = 16*h + 2*q;
                *(u64*)&ps[ row     *RPAD + (lane << 1)] = p0;
                *(u64*)&ps[(row + 1)*RPAD + (lane << 1)] = p1;
                vprev = va[q].y;
            }
        }
        __syncwarp();
        // lane t reduces row t (timestep base+t): 16x LDS.128, packed adds
        const ulonglong2* row = (const ulonglong2*)&ps[lane * RPAD];
        u64 a0 = 0ull, a1 = 0ull;
        #pragma unroll
        for (int q = 0; q < 16; ++q) {
            ulonglong2 rr = row[q];
            a0 = f2add(a0, rr.x);
            a1 = f2add(a1, rr.y);
        }
        float2 sf = f2unpack(f2add(a0, a1));
        float vv  = vs[base + lane].x;
        float s   = sf.x + sf.y + dc * vv;   // + D*v skip (deferred)
        // gelu (tanh approx), overflow-safe
        float a2 = 1.5957691216057308f * fmaf(0.044715f * s, s * s, s);
        float e  = __expf(a2);
        float th = 1.0f - __fdividef(2.0f, e + 1.0f);
        yp[base + lane] = 0.5f * s * (1.0f + th);
        __syncwarp();
    }
}

// ---------------- out[b,o,l] = sum_c W[c,o] * yT[b,c,l] + bias[o] ----------------
// 64(o) x 128(l) tile, BK=8, 256 threads, 4x8 microtile, reg->smem double buffer
__global__ __launch_bounds__(256) void gemm_kernel(const float* __restrict__ W,
                                                   const float* __restrict__ bias,
                                                   float* __restrict__ out) {
    __shared__ float Ws[2][8][64];
    __shared__ float Ys[2][8][128];
    int b  = blockIdx.z;
    int oo = blockIdx.y << 6;
    int ll = blockIdx.x << 7;
    int tid = threadIdx.x;
    int tx = tid & 15, ty = tid >> 4;   // ty 0..15 (o), tx 0..15 (l)
    int lr  = tid >> 5;                 // 0..7
    int lwc = (tid & 31) << 1;          // 0..62   (float2 for W)
    int lyc = (tid & 31) << 2;          // 0..124  (float4 for Y)

    const float* Wp = W + (size_t)lr * OUTc + oo + lwc;
    const float* Yp = g_yT + ((size_t)b * Hc + lr) * Lt + ll + lyc;

    float2 wreg = *(const float2*)Wp;
    float4 yreg = *(const float4*)Yp;

    float acc[4][8];
    #pragma unroll
    for (int i = 0; i < 4; ++i)
        #pragma unroll
        for (int j = 0; j < 8; ++j) acc[i][j] = 0.f;

    int buf = 0;
    for (int kk = 0; kk < Hc; kk += 8) {
        *(float2*)&Ws[buf][lr][lwc] = wreg;
        *(float4*)&Ys[buf][lr][lyc] = yreg;
        __syncthreads();
        if (kk + 8 < Hc) {
            wreg = *(const float2*)(Wp + (size_t)(kk + 8) * OUTc);
            yreg = *(const float4*)(Yp + (size_t)(kk + 8) * Lt);
        }
        #pragma unroll
        for (int k = 0; k < 8; ++k) {
            float4 wv = *(float4*)&Ws[buf][k][ty << 2];
            float4 y0 = *(float4*)&Ys[buf][k][tx << 3];
            float4 y1 = *(float4*)&Ys[buf][k][(tx << 3) + 4];
            float wa[4] = {wv.x, wv.y, wv.z, wv.w};
            float ya[8] = {y0.x, y0.y, y0.z, y0.w, y1.x, y1.y, y1.z, y1.w};
            #pragma unroll
            for (int i = 0; i < 4; ++i)
                #pragma unroll
                for (int j = 0; j < 8; ++j)
                    acc[i][j] = fmaf(wa[i], ya[j], acc[i][j]);
        }
        buf ^= 1;
    }

    #pragma unroll
    for (int i = 0; i < 4; ++i) {
        int o = oo + (ty << 2) + i;
        float bo = __ldg(&bias[o]);
        float* op = out + ((size_t)b * OUTc + o) * Lt + ll + (tx << 3);
        float4 r0 = make_float4(acc[i][0]+bo, acc[i][1]+bo, acc[i][2]+bo, acc[i][3]+bo);
        float4 r1 = make_float4(acc[i][4]+bo, acc[i][5]+bo, acc[i][6]+bo, acc[i][7]+bo);
        *(float4*)op       = r0;
        *(float4*)(op + 4) = r1;
    }
}

// ---------------- launch ----------------
extern "C" void kernel_launch(void* const* d_in, const int* in_sizes, int n_in,
                              void* d_out, int out_size) {
    const float* x      = (const float*)d_in[0];
    const float* log_dt = (const float*)d_in[1];
    const float* A_re   = (const float*)d_in[2];
    const float* A_im   = (const float*)d_in[3];
    const float* C_re   = (const float*)d_in[4];
    const float* C_im   = (const float*)d_in[5];
    const float* D      = (const float*)d_in[6];
    const float* W      = (const float*)d_in[7];
    const float* bias   = (const float*)d_in[8];
    float* out = (float*)d_out;

    prep_emb_kernel<<<(3*16*CH3 + 255)/256, 256>>>();
    prep_ct_kernel<<<(Hc*Nst + 255)/256, 256>>>(log_dt, A_re, A_im, C_re, C_im);
    v_kernel<<<(BSz*Hc*Lt/4 + 255)/256, 256>>>(x);
    ssm_kernel<<<BSz*Hc, 32>>>(D);                               // one warp per (b,c)
    gemm_kernel<<<dim3(Lt/128, OUTc/64, BSz), 256>>>(W, bias, out);
}

// round 4
// speedup vs baseline: 1.2194x; 1.2194x over previous
#include <cuda_runtime.h>
#include <math.h>

#define Hc   1024
#define Nst  64
#define Lt   4096
#define OUTc 512
#define BSz  2
#define CH3  342   // per-axis posenc channels
#define Tc   512   // chunk length
#define NCH  8     // Lt / Tc

typedef unsigned long long u64;

// ---------------- f32x2 packed math (sm_103a FFMA2 path) ----------------
__device__ __forceinline__ u64 f2fma(u64 a, u64 b, u64 c) {
    u64 d; asm("fma.rn.f32x2 %0,%1,%2,%3;" : "=l"(d) : "l"(a), "l"(b), "l"(c)); return d;
}
__device__ __forceinline__ u64 f2mul(u64 a, u64 b) {
    u64 d; asm("mul.rn.f32x2 %0,%1,%2;" : "=l"(d) : "l"(a), "l"(b)); return d;
}
__device__ __forceinline__ u64 f2add(u64 a, u64 b) {
    u64 d; asm("add.rn.f32x2 %0,%1,%2;" : "=l"(d) : "l"(a), "l"(b)); return d;
}
__device__ __forceinline__ u64 f2pack(float lo, float hi) {
    u64 d; asm("mov.b64 %0,{%1,%2};" : "=l"(d) : "f"(lo), "f"(hi)); return d;
}
__device__ __forceinline__ float2 f2unpack(u64 v) {
    float2 r; asm("mov.b64 {%0,%1},%2;" : "=f"(r.x), "=f"(r.y) : "l"(v)); return r;
}

// ---------------- scratch ----------------
__device__ float2 g_v2[BSz*Hc*Lt];    // v duplicated {v,v}, layout (b, c, l)
__device__ float  g_yT[BSz*Hc*Lt];    // gelu(conv + D*v), layout (b, c, l)
__device__ float g_wre[Hc*Nst],  g_wim[Hc*Nst];
__device__ float g_wTre[Hc*Nst], g_wTim[Hc*Nst];   // w^Tc
__device__ float g_ctre[Hc*Nst], g_ctim[Hc*Nst];
__device__ float g_emb[3*16*CH3];     // [axis][pos][k]
__device__ u64 g_csr[BSz*Hc*NCH*32], g_csi[BSz*Hc*NCH*32];  // chunk contributions B_k
__device__ u64 g_s0r[BSz*Hc*NCH*32], g_s0i[BSz*Hc*NCH*32];  // chunk start states

// ---------------- posenc tables ----------------
__global__ void prep_emb_kernel() {
    int idx = blockIdx.x * blockDim.x + threadIdx.x;
    if (idx >= 3*16*CH3) return;
    int k   = idx % CH3;
    int pos = (idx / CH3) % 16;
    int i   = k >> 1;
    float freq = expf(-logf(10000.0f) * (float)(2*i) / (float)CH3);
    float arg  = (float)pos * freq;
    g_emb[idx] = (k & 1) ? cosf(arg) : sinf(arg);
}

// ---------------- discretize (double precision for w^Tc accuracy) ----------------
__global__ void prep_ct_kernel(const float* __restrict__ log_dt,
                               const float* __restrict__ Are, const float* __restrict__ Aim,
                               const float* __restrict__ Cre, const float* __restrict__ Cim) {
    int idx = blockIdx.x * blockDim.x + threadIdx.x;
    if (idx >= Hc*Nst) return;
    int c = idx >> 6;
    double dt  = exp((double)log_dt[c]);
    double ar  = (double)Are[idx], ai = (double)Aim[idx];
    double dar = dt*ar, dai = dt*ai;
    double er  = exp(dar);
    double sn  = sin(dai), cs = cos(dai);
    double wr = er*cs, wi = er*sn;
    g_wre[idx] = (float)wr; g_wim[idx] = (float)wi;
    // w^Tc = exp(Tc*dt*A), computed in double (accurate range reduction)
    double erT = exp((double)Tc * dar);
    double snT = sin((double)Tc * dai), csT = cos((double)Tc * dai);
    g_wTre[idx] = (float)(erT*csT); g_wTim[idx] = (float)(erT*snT);
    // Ct' = 2*C*(w-1)/A
    double nr = wr - 1.0, ni = wi;
    double inv = 1.0 / (ar*ar + ai*ai);
    double qr = (nr*ar + ni*ai) * inv;
    double qi = (ni*ar - nr*ai) * inv;
    double cr = (double)Cre[idx], ci = (double)Cim[idx];
    g_ctre[idx] = (float)(2.0*(cr*qr - ci*qi));
    g_ctim[idx] = (float)(2.0*(cr*qi + ci*qr));
}

// ---------------- v = x + posenc, duplicated {v,v}, fully coalesced ----------------
__global__ void v_kernel(const float* __restrict__ x) {
    int i2 = blockIdx.x * blockDim.x + threadIdx.x;   // one float4 out = 2 l positions
    if (i2 >= BSz*Hc*Lt/2) return;
    int l2 = i2 & (Lt/2 - 1);
    int c  = (i2 >> 11) & (Hc - 1);
    int l  = l2 << 1;
    int lw = l & 15, lh = (l >> 4) & 15, lf = l >> 8;
    float2 xv = ((const float2*)x)[i2];
    float p0, p1;
    if (c < CH3) {
        float e = g_emb[lf*CH3 + c]; p0 = p1 = e;
    } else if (c < 2*CH3) {
        float e = g_emb[(16 + lh)*CH3 + (c - CH3)]; p0 = p1 = e;
    } else {
        int k = c - 2*CH3;
        const float* ez = g_emb + 32*CH3 + k;
        p0 = ez[lw*CH3]; p1 = ez[(lw+1)*CH3];   // lw even, so lw+1 <= 15
    }
    float v0 = xv.x + p0, v1 = xv.y + p1;
    ((float4*)g_v2)[i2] = make_float4(v0, v0, v1, v1);
}

// ---------------- pass A: per-chunk recurrence from zero -> B_k ----------------
__global__ __launch_bounds__(32) void ssmA_kernel() {
    int gid  = blockIdx.x;               // (b*Hc+c)*NCH + k
    int lane = threadIdx.x;
    int wid  = gid >> 3, k = gid & (NCH - 1);
    int c    = wid & (Hc - 1);
    int n0   = (c << 6) + lane;

    u64 Wr  = f2pack( g_wre[n0],  g_wre[n0+32]);
    u64 Wi  = f2pack( g_wim[n0],  g_wim[n0+32]);
    u64 Win = f2pack(-g_wim[n0], -g_wim[n0+32]);

    const ulonglong2* vp = (const ulonglong2*)(g_v2 + (size_t)wid * Lt + k * Tc);
    u64 Sr = 0ull, Si = 0ull;

    for (int it = 0; it < Tc/16; ++it) {
        ulonglong2 va[8];
        #pragma unroll
        for (int q = 0; q < 8; ++q) va[q] = vp[it*8 + q];
        #pragma unroll
        for (int q = 0; q < 8; ++q) {
            { u64 t = f2fma(Win, Si, va[q].x); u64 u = f2mul(Wr, Si);
              u64 n = f2fma(Wr, Sr, t); Si = f2fma(Wi, Sr, u); Sr = n; }
            { u64 t = f2fma(Win, Si, va[q].y); u64 u = f2mul(Wr, Si);
              u64 n = f2fma(Wr, Sr, t); Si = f2fma(Wi, Sr, u); Sr = n; }
        }
    }
    g_csr[gid*32 + lane] = Sr;
    g_csi[gid*32 + lane] = Si;
}

// ---------------- pass B: scan chunk-start states ----------------
__global__ __launch_bounds__(32) void ssmB_kernel() {
    int wid  = blockIdx.x;               // b*Hc + c
    int lane = threadIdx.x;
    int c    = wid & (Hc - 1);
    int n0   = (c << 6) + lane;

    u64 WTr  = f2pack( g_wTre[n0],  g_wTre[n0+32]);
    u64 WTi  = f2pack( g_wTim[n0],  g_wTim[n0+32]);
    u64 WTin = f2pack(-g_wTim[n0], -g_wTim[n0+32]);

    u64 sr = 0ull, si = 0ull;
    #pragma unroll
    for (int k = 0; k < NCH; ++k) {
        int idx = (wid*NCH + k)*32 + lane;
        g_s0r[idx] = sr; g_s0i[idx] = si;
        u64 br = g_csr[idx], bi = g_csi[idx];
        u64 t  = f2fma(WTin, si, br);
        u64 u  = f2fma(WTr,  si, bi);
        u64 ns = f2fma(WTr,  sr, t);
        si     = f2fma(WTi,  sr, u);
        sr     = ns;
    }
}

// ---------------- pass C: recurrence with init state + dot + skip + gelu ----------------
#define RPAD 68   // words per reduce row (32 u64 = 64 words + 4 pad)

__global__ __launch_bounds__(32) void ssmC_kernel(const float* __restrict__ D) {
    __shared__ float ps[32*RPAD];
    int gid  = blockIdx.x;               // (b*Hc+c)*NCH + k
    int lane = threadIdx.x;
    int wid  = gid >> 3, k = gid & (NCH - 1);
    int c    = wid & (Hc - 1);
    int n0   = (c << 6) + lane;

    u64 Wr  = f2pack( g_wre[n0],   g_wre[n0+32]);
    u64 Wi  = f2pack( g_wim[n0],   g_wim[n0+32]);
    u64 Win = f2pack(-g_wim[n0],  -g_wim[n0+32]);
    u64 Cr  = f2pack( g_ctre[n0],  g_ctre[n0+32]);
    u64 Cin = f2pack(-g_ctim[n0], -g_ctim[n0+32]);
    float dc = D[c];

    const ulonglong2* vp = (const ulonglong2*)(g_v2 + (size_t)wid * Lt + k * Tc);
    const float2*     vs = g_v2 + (size_t)wid * Lt + k * Tc;
    float*            yp = g_yT + (size_t)wid * Lt + k * Tc;

    u64 Sr = g_s0r[gid*32 + lane];
    u64 Si = g_s0i[gid*32 + lane];

    for (int base = 0; base < Tc; base += 32) {
        #pragma unroll
        for (int h = 0; h < 2; ++h) {
            ulonglong2 va[8];
            #pragma unroll
            for (int q = 0; q < 8; ++q) va[q] = vp[((base + 16*h) >> 1) + q];
            #pragma unroll
            for (int q = 0; q < 8; ++q) {
                int row = 16*h + 2*q;
                { u64 t = f2fma(Win, Si, va[q].x); u64 u = f2mul(Wr, Si);
                  u64 n = f2fma(Wr, Sr, t); Si = f2fma(Wi, Sr, u); Sr = n;
                  u64 p = f2fma(Cin, Si, f2mul(Cr, Sr));
                  *(u64*)&ps[row*RPAD + (lane << 1)] = p; }
                { u64 t = f2fma(Win, Si, va[q].y); u64 u = f2mul(Wr, Si);
                  u64 n = f2fma(Wr, Sr, t); Si = f2fma(Wi, Sr, u); Sr = n;
                  u64 p = f2fma(Cin, Si, f2mul(Cr, Sr));
                  *(u64*)&ps[(row+1)*RPAD + (lane << 1)] = p; }
            }
        }
        __syncwarp();
        // lane t reduces row t (timestep base+t): 16x LDS.128, packed adds
        const ulonglong2* row = (const ulonglong2*)&ps[lane * RPAD];
        u64 a0 = 0ull, a1 = 0ull;
        #pragma unroll
        for (int q = 0; q < 16; ++q) {
            ulonglong2 rr = row[q];
            a0 = f2add(a0, rr.x);
            a1 = f2add(a1, rr.y);
        }
        float2 sf = f2unpack(f2add(a0, a1));
        float vv  = vs[base + lane].x;
        float s   = sf.x + sf.y + dc * vv;   // + D*v skip (deferred)
        // gelu (tanh approx), overflow-safe
        float a2 = 1.5957691216057308f * fmaf(0.044715f * s, s * s, s);
        float e  = __expf(a2);
        float th = 1.0f - __fdividef(2.0f, e + 1.0f);
        yp[base + lane] = 0.5f * s * (1.0f + th);
        __syncwarp();
    }
}

// ---------------- out[b,o,l] = sum_c W[c,o] * yT[b,c,l] + bias[o] ----------------
// 128(o) x 128(l) tile, BK=8, 256 threads, 8x8 microtile, reg->smem double buffer
__global__ __launch_bounds__(256) void gemm_kernel(const float* __restrict__ W,
                                                   const float* __restrict__ bias,
                                                   float* __restrict__ out) {
    __shared__ float Ws[2][8][128];
    __shared__ float Ys[2][8][128];
    int b  = blockIdx.z;
    int oo = blockIdx.y << 7;
    int ll = blockIdx.x << 7;
    int tid = threadIdx.x;
    int tx = tid & 15, ty = tid >> 4;
    int lr = tid >> 5;              // load row 0..7
    int lc = (tid & 31) << 2;       // load col 0..124

    const float* Wp = W + (size_t)lr * OUTc + oo + lc;
    const float* Yp = g_yT + ((size_t)b * Hc + lr) * Lt + ll + lc;

    float4 wreg = *(const float4*)Wp;
    float4 yreg = *(const float4*)Yp;

    float acc[8][8];
    #pragma unroll
    for (int i = 0; i < 8; ++i)
        #pragma unroll
        for (int j = 0; j < 8; ++j) acc[i][j] = 0.f;

    int buf = 0;
    for (int kk = 0; kk < Hc; kk += 8) {
        *(float4*)&Ws[buf][lr][lc] = wreg;
        *(float4*)&Ys[buf][lr][lc] = yreg;
        __syncthreads();
        if (kk + 8 < Hc) {
            wreg = *(const float4*)(Wp + (size_t)(kk + 8) * OUTc);
            yreg = *(const float4*)(Yp + (size_t)(kk + 8) * Lt);
        }
        #pragma unroll
        for (int k = 0; k < 8; ++k) {
            float4 w0 = *(float4*)&Ws[buf][k][ty << 2];
            float4 w1 = *(float4*)&Ws[buf][k][(ty << 2) + 64];
            float4 y0 = *(float4*)&Ys[buf][k][tx << 2];
            float4 y1 = *(float4*)&Ys[buf][k][(tx << 2) + 64];
            float wa[8] = {w0.x, w0.y, w0.z, w0.w, w1.x, w1.y, w1.z, w1.w};
            float ya[8] = {y0.x, y0.y, y0.z, y0.w, y1.x, y1.y, y1.z, y1.w};
            #pragma unroll
            for (int i = 0; i < 8; ++i)
                #pragma unroll
                for (int j = 0; j < 8; ++j)
                    acc[i][j] = fmaf(wa[i], ya[j], acc[i][j]);
        }
        buf ^= 1;
    }

    #pragma unroll
    for (int i = 0; i < 8; ++i) {
        int o = oo + (ty << 2) + ((i < 4) ? i : 60 + i);   // i>=4 -> +64+(i-4)
        float bo = __ldg(&bias[o]);
        float* op = out + ((size_t)b * OUTc + o) * Lt + ll + (tx << 2);
        float4 r0 = make_float4(acc[i][0]+bo, acc[i][1]+bo, acc[i][2]+bo, acc[i][3]+bo);
        float4 r1 = make_float4(acc[i][4]+bo, acc[i][5]+bo, acc[i][6]+bo, acc[i][7]+bo);
        *(float4*)op        = r0;
        *(float4*)(op + 64) = r1;
    }
}

// ---------------- launch ----------------
extern "C" void kernel_launch(void* const* d_in, const int* in_sizes, int n_in,
                              void* d_out, int out_size) {
    const float* x      = (const float*)d_in[0];
    const float* log_dt = (const float*)d_in[1];
    const float* A_re   = (const float*)d_in[2];
    const float* A_im   = (const float*)d_in[3];
    const float* C_re   = (const float*)d_in[4];
    const float* C_im   = (const float*)d_in[5];
    const float* D      = (const float*)d_in[6];
    const float* W      = (const float*)d_in[7];
    const float* bias   = (const float*)d_in[8];
    float* out = (float*)d_out;

    prep_emb_kernel<<<(3*16*CH3 + 255)/256, 256>>>();
    prep_ct_kernel<<<(Hc*Nst + 255)/256, 256>>>(log_dt, A_re, A_im, C_re, C_im);
    v_kernel<<<(BSz*Hc*Lt/2 + 255)/256, 256>>>(x);
    ssmA_kernel<<<BSz*Hc*NCH, 32>>>();
    ssmB_kernel<<<BSz*Hc, 32>>>();
    ssmC_kernel<<<BSz*Hc*NCH, 32>>>(D);
    gemm_kernel<<<dim3(Lt/128, OUTc/128, BSz), 256>>>(W, bias, out);
}

// round 5
// speedup vs baseline: 1.5307x; 1.2553x over previous
#include <cuda_runtime.h>
#include <math.h>
#include <stdint.h>

#define Hc   1024
#define Nst  64
#define Lt   4096
#define OUTc 512
#define BSz  2
#define CH3  342   // per-axis posenc channels
#define Tc   512   // chunk length
#define NCH  8     // Lt / Tc

typedef unsigned long long u64;

// ---------------- f32x2 packed math (sm_103a FFMA2 path) ----------------
__device__ __forceinline__ u64 f2fma(u64 a, u64 b, u64 c) {
    u64 d; asm("fma.rn.f32x2 %0,%1,%2,%3;" : "=l"(d) : "l"(a), "l"(b), "l"(c)); return d;
}
__device__ __forceinline__ u64 f2mul(u64 a, u64 b) {
    u64 d; asm("mul.rn.f32x2 %0,%1,%2;" : "=l"(d) : "l"(a), "l"(b)); return d;
}
__device__ __forceinline__ u64 f2add(u64 a, u64 b) {
    u64 d; asm("add.rn.f32x2 %0,%1,%2;" : "=l"(d) : "l"(a), "l"(b)); return d;
}
__device__ __forceinline__ u64 f2pack(float lo, float hi) {
    u64 d; asm("mov.b64 %0,{%1,%2};" : "=l"(d) : "f"(lo), "f"(hi)); return d;
}
__device__ __forceinline__ float2 f2unpack(u64 v) {
    float2 r; asm("mov.b64 {%0,%1},%2;" : "=f"(r.x), "=f"(r.y) : "l"(v)); return r;
}

// ---------------- scratch ----------------
__device__ float2 g_v2[BSz*Hc*Lt];    // v duplicated {v,v}, layout (b, c, l)
__device__ float  g_yT[BSz*Hc*Lt];    // gelu(conv + D*v), layout (b, c, l)
__device__ float g_wre[Hc*Nst],  g_wim[Hc*Nst];
__device__ float g_w2re[Hc*Nst], g_w2im[Hc*Nst];   // w^2
__device__ float g_wTre[Hc*Nst], g_wTim[Hc*Nst];   // w^Tc
__device__ float g_ctre[Hc*Nst], g_ctim[Hc*Nst];
__device__ float g_emb[3*16*CH3];     // [axis][pos][k]
__device__ u64 g_csr[BSz*Hc*NCH*32], g_csi[BSz*Hc*NCH*32];  // chunk contributions
__device__ u64 g_s0r[BSz*Hc*NCH*32], g_s0i[BSz*Hc*NCH*32];  // chunk start states

// ---------------- posenc tables ----------------
__global__ void prep_emb_kernel() {
    int idx = blockIdx.x * blockDim.x + threadIdx.x;
    if (idx >= 3*16*CH3) return;
    int k   = idx % CH3;
    int pos = (idx / CH3) % 16;
    int i   = k >> 1;
    float freq = expf(-logf(10000.0f) * (float)(2*i) / (float)CH3);
    float arg  = (float)pos * freq;
    g_emb[idx] = (k & 1) ? cosf(arg) : sinf(arg);
}

// ---------------- discretize (double precision for w^2 / w^Tc accuracy) ----------------
__global__ void prep_ct_kernel(const float* __restrict__ log_dt,
                               const float* __restrict__ Are, const float* __restrict__ Aim,
                               const float* __restrict__ Cre, const float* __restrict__ Cim) {
    int idx = blockIdx.x * blockDim.x + threadIdx.x;
    if (idx >= Hc*Nst) return;
    int c = idx >> 6;
    double dt  = exp((double)log_dt[c]);
    double ar  = (double)Are[idx], ai = (double)Aim[idx];
    double dar = dt*ar, dai = dt*ai;
    double er  = exp(dar);
    double sn  = sin(dai), cs = cos(dai);
    double wr = er*cs, wi = er*sn;
    g_wre[idx] = (float)wr; g_wim[idx] = (float)wi;
    double er2 = exp(2.0*dar);
    double sn2 = sin(2.0*dai), cs2 = cos(2.0*dai);
    g_w2re[idx] = (float)(er2*cs2); g_w2im[idx] = (float)(er2*sn2);
    double erT = exp((double)Tc * dar);
    double snT = sin((double)Tc * dai), csT = cos((double)Tc * dai);
    g_wTre[idx] = (float)(erT*csT); g_wTim[idx] = (float)(erT*snT);
    double nr = wr - 1.0, ni = wi;
    double inv = 1.0 / (ar*ar + ai*ai);
    double qr = (nr*ar + ni*ai) * inv;
    double qi = (ni*ar - nr*ai) * inv;
    double cr = (double)Cre[idx], ci = (double)Cim[idx];
    g_ctre[idx] = (float)(2.0*(cr*qr - ci*qi));
    g_ctim[idx] = (float)(2.0*(cr*qi + ci*qr));
}

// ---------------- v = x + posenc, duplicated {v,v}, coalesced ----------------
__global__ void v_kernel(const float* __restrict__ x) {
    int i2 = blockIdx.x * blockDim.x + threadIdx.x;   // one float4 out = 2 l positions
    if (i2 >= BSz*Hc*Lt/2) return;
    int l2 = i2 & (Lt/2 - 1);
    int c  = (i2 >> 11) & (Hc - 1);
    int l  = l2 << 1;
    int lw = l & 15, lh = (l >> 4) & 15, lf = l >> 8;
    float2 xv = ((const float2*)x)[i2];
    float p0, p1;
    if (c < CH3) {
        float e = g_emb[lf*CH3 + c]; p0 = p1 = e;
    } else if (c < 2*CH3) {
        float e = g_emb[(16 + lh)*CH3 + (c - CH3)]; p0 = p1 = e;
    } else {
        int k = c - 2*CH3;
        const float* ez = g_emb + 32*CH3 + k;
        p0 = ez[lw*CH3]; p1 = ez[(lw+1)*CH3];
    }
    float v0 = xv.x + p0, v1 = xv.y + p1;
    ((float4*)g_v2)[i2] = make_float4(v0, v0, v1, v1);
}

// ---------------- pass A: per-chunk recurrence from zero -> B_k (decim-by-2) ----------------
__global__ __launch_bounds__(32) void ssmA_kernel() {
    int gid  = blockIdx.x;               // (b*Hc+c)*NCH + k
    int lane = threadIdx.x;
    int wid  = gid >> 3, k = gid & (NCH - 1);
    int c    = wid & (Hc - 1);
    int n0   = (c << 6) + lane;

    u64 Wr   = f2pack( g_wre[n0],   g_wre[n0+32]);
    u64 Wi   = f2pack( g_wim[n0],   g_wim[n0+32]);
    u64 W2r  = f2pack( g_w2re[n0],  g_w2re[n0+32]);
    u64 W2i  = f2pack( g_w2im[n0],  g_w2im[n0+32]);
    u64 W2in = f2pack(-g_w2im[n0], -g_w2im[n0+32]);

    const ulonglong2* vp = (const ulonglong2*)(g_v2 + (size_t)wid * Lt + k * Tc);
    u64 Sr = 0ull, Si = 0ull;

    for (int it = 0; it < Tc/16; ++it) {
        ulonglong2 va[8];
        #pragma unroll
        for (int q = 0; q < 8; ++q) va[q] = vp[it*8 + q];
        #pragma unroll
        for (int q = 0; q < 8; ++q) {
            // two steps at once: s = w2*s + (w*v0 + v1)
            u64 ir  = f2fma(Wr, va[q].x, va[q].y);   // wr*v0 + v1
            u64 ii  = f2mul(Wi, va[q].x);            // wi*v0
            u64 tr  = f2fma(W2in, Si, ir);
            u64 nSr = f2fma(W2r,  Sr, tr);
            u64 ti  = f2fma(W2r,  Si, ii);
            Si      = f2fma(W2i,  Sr, ti);
            Sr      = nSr;
        }
    }
    g_csr[gid*32 + lane] = Sr;
    g_csi[gid*32 + lane] = Si;
}

// ---------------- pass B: scan chunk-start states ----------------
__global__ __launch_bounds__(32) void ssmB_kernel() {
    int wid  = blockIdx.x;               // b*Hc + c
    int lane = threadIdx.x;
    int c    = wid & (Hc - 1);
    int n0   = (c << 6) + lane;

    u64 WTr  = f2pack( g_wTre[n0],  g_wTre[n0+32]);
    u64 WTi  = f2pack( g_wTim[n0],  g_wTim[n0+32]);
    u64 WTin = f2pack(-g_wTim[n0], -g_wTim[n0+32]);

    u64 sr = 0ull, si = 0ull;
    #pragma unroll
    for (int k = 0; k < NCH; ++k) {
        int idx = (wid*NCH + k)*32 + lane;
        g_s0r[idx] = sr; g_s0i[idx] = si;
        u64 br = g_csr[idx], bi = g_csi[idx];
        u64 t  = f2fma(WTin, si, br);
        u64 u  = f2fma(WTr,  si, bi);
        u64 ns = f2fma(WTr,  sr, t);
        si     = f2fma(WTi,  sr, u);
        sr     = ns;
    }
}

// ---------------- pass C: recurrence with init state + dot + skip + gelu ----------------
#define RP2 36   // words per reduce row (32 floats + 4 pad); 144B rows keep 16B align

__global__ __launch_bounds__(32) void ssmC_kernel(const float* __restrict__ D) {
    __shared__ float ps[32*RP2];
    int gid  = blockIdx.x;               // (b*Hc+c)*NCH + k
    int lane = threadIdx.x;
    int wid  = gid >> 3, k = gid & (NCH - 1);
    int c    = wid & (Hc - 1);
    int n0   = (c << 6) + lane;

    u64 Wr  = f2pack( g_wre[n0],   g_wre[n0+32]);
    u64 Wi  = f2pack( g_wim[n0],   g_wim[n0+32]);
    u64 Win = f2pack(-g_wim[n0],  -g_wim[n0+32]);
    u64 Cr  = f2pack( g_ctre[n0],  g_ctre[n0+32]);
    u64 Cin = f2pack(-g_ctim[n0], -g_ctim[n0+32]);
    float dc = D[c];

    const ulonglong2* vp = (const ulonglong2*)(g_v2 + (size_t)wid * Lt + k * Tc);
    const float2*     vs = g_v2 + (size_t)wid * Lt + k * Tc;
    float*            yp = g_yT + (size_t)wid * Lt + k * Tc;

    u64 Sr = g_s0r[gid*32 + lane];
    u64 Si = g_s0i[gid*32 + lane];

    for (int base = 0; base < Tc; base += 32) {
        #pragma unroll
        for (int h = 0; h < 2; ++h) {
            ulonglong2 va[8];
            #pragma unroll
            for (int q = 0; q < 8; ++q) va[q] = vp[((base + 16*h) >> 1) + q];
            #pragma unroll
            for (int q = 0; q < 8; ++q) {
                int row = 16*h + 2*q;
                { u64 t = f2fma(Win, Si, va[q].x); u64 u = f2mul(Wr, Si);
                  u64 n = f2fma(Wr, Sr, t); Si = f2fma(Wi, Sr, u); Sr = n;
                  float2 pf = f2unpack(f2fma(Cin, Si, f2mul(Cr, Sr)));
                  ps[row*RP2 + lane] = pf.x + pf.y; }
                { u64 t = f2fma(Win, Si, va[q].y); u64 u = f2mul(Wr, Si);
                  u64 n = f2fma(Wr, Sr, t); Si = f2fma(Wi, Sr, u); Sr = n;
                  float2 pf = f2unpack(f2fma(Cin, Si, f2mul(Cr, Sr)));
                  ps[(row+1)*RP2 + lane] = pf.x + pf.y; }
            }
        }
        __syncwarp();
        // lane t reduces row t (timestep base+t): 8x LDS.128, packed adds
        const ulonglong2* row = (const ulonglong2*)&ps[lane * RP2];
        u64 a0 = 0ull, a1 = 0ull;
        #pragma unroll
        for (int q = 0; q < 8; ++q) {
            ulonglong2 rr = row[q];
            a0 = f2add(a0, rr.x);
            a1 = f2add(a1, rr.y);
        }
        float2 sf = f2unpack(f2add(a0, a1));
        float vv  = vs[base + lane].x;
        float s   = sf.x + sf.y + dc * vv;   // + D*v skip (deferred)
        float a2 = 1.5957691216057308f * fmaf(0.044715f * s, s * s, s);
        float e  = __expf(a2);
        float th = 1.0f - __fdividef(2.0f, e + 1.0f);
        yp[base + lane] = 0.5f * s * (1.0f + th);
        __syncwarp();
    }
}

// ---------------- tf32 tensor-core GEMM ----------------
// out[b,o,l] = sum_k W[k,o] * yT[b,k,l] + bias[o]
// tile: 64(o=M) x 128(l=N), BK=8, 128 threads = 4 warps, warp tile 32x64
__global__ __launch_bounds__(128) void gemm_kernel(const float* __restrict__ W,
                                                   const float* __restrict__ bias,
                                                   float* __restrict__ out) {
    __shared__ float Ws[2][8][68];    // [k][o], pad 68
    __shared__ float Ys[2][8][132];   // [k][l], pad 132
    int b  = blockIdx.z;
    int oo = blockIdx.y << 6;
    int ll = blockIdx.x << 7;
    int t  = threadIdx.x;
    int lane = t & 31, wid = t >> 5;
    int om = (wid & 1) << 5;     // 0 / 32
    int on = (wid >> 1) << 6;    // 0 / 64
    int gID = lane >> 2, tig = lane & 3;

    // stage-load addressing
    int wr_ = t >> 4;                 // 0..7
    int wc  = (t & 15) << 2;          // 0..60
    int yc  = (t & 15) << 3;          // 0..120
    const float* Wp = W + (size_t)wr_ * OUTc + oo + wc;
    const float* Yp = g_yT + ((size_t)b * Hc + wr_) * Lt + ll + yc;

    float4 wv  = *(const float4*)Wp;
    float4 yv0 = *(const float4*)Yp;
    float4 yv1 = *(const float4*)(Yp + 4);

    float acc[2][8][4];
    #pragma unroll
    for (int mt = 0; mt < 2; ++mt)
        #pragma unroll
        for (int nt = 0; nt < 8; ++nt)
            #pragma unroll
            for (int r = 0; r < 4; ++r) acc[mt][nt][r] = 0.f;

    int buf = 0;
    for (int s = 0; s < Hc/8; ++s) {
        *(float4*)&Ws[buf][wr_][wc]     = wv;
        *(float4*)&Ys[buf][wr_][yc]     = yv0;
        *(float4*)&Ys[buf][wr_][yc + 4] = yv1;
        __syncthreads();
        if (s + 1 < Hc/8) {
            size_t ko = (size_t)(s + 1) * 8;
            wv  = *(const float4*)(Wp + ko * OUTc);
            yv0 = *(const float4*)(Yp + ko * Lt);
            yv1 = *(const float4*)(Yp + ko * Lt + 4);
        }
        // fragments (tf32 fast path: raw fp32 bits, HW truncates mantissa)
        uint32_t a[2][4];
        #pragma unroll
        for (int mt = 0; mt < 2; ++mt) {
            int r0 = om + (mt << 4) + gID;
            a[mt][0] = __float_as_uint(Ws[buf][tig    ][r0]);
            a[mt][1] = __float_as_uint(Ws[buf][tig    ][r0 + 8]);
            a[mt][2] = __float_as_uint(Ws[buf][tig + 4][r0]);
            a[mt][3] = __float_as_uint(Ws[buf][tig + 4][r0 + 8]);
        }
        uint32_t bf[8][2];
        #pragma unroll
        for (int nt = 0; nt < 8; ++nt) {
            int cn = on + (nt << 3) + gID;
            bf[nt][0] = __float_as_uint(Ys[buf][tig    ][cn]);
            bf[nt][1] = __float_as_uint(Ys[buf][tig + 4][cn]);
        }
        #pragma unroll
        for (int mt = 0; mt < 2; ++mt)
            #pragma unroll
            for (int nt = 0; nt < 8; ++nt) {
                asm("mma.sync.aligned.m16n8k8.row.col.f32.tf32.tf32.f32 "
                    "{%0,%1,%2,%3},{%4,%5,%6,%7},{%8,%9},{%0,%1,%2,%3};"
                    : "+f"(acc[mt][nt][0]), "+f"(acc[mt][nt][1]),
                      "+f"(acc[mt][nt][2]), "+f"(acc[mt][nt][3])
                    : "r"(a[mt][0]), "r"(a[mt][1]), "r"(a[mt][2]), "r"(a[mt][3]),
                      "r"(bf[nt][0]), "r"(bf[nt][1]));
            }
        buf ^= 1;
    }

    // epilogue
    #pragma unroll
    for (int mt = 0; mt < 2; ++mt) {
        int o0 = oo + om + (mt << 4) + gID;
        float b0 = __ldg(&bias[o0]);
        float b8 = __ldg(&bias[o0 + 8]);
        float* r0p = out + ((size_t)b * OUTc + o0)     * Lt + ll + on + (tig << 1);
        float* r8p = out + ((size_t)b * OUTc + o0 + 8) * Lt + ll + on + (tig << 1);
        #pragma unroll
        for (int nt = 0; nt < 8; ++nt) {
            float2 v0 = make_float2(acc[mt][nt][0] + b0, acc[mt][nt][1] + b0);
            float2 v8 = make_float2(acc[mt][nt][2] + b8, acc[mt][nt][3] + b8);
            *(float2*)(r0p + (nt << 3)) = v0;
            *(float2*)(r8p + (nt << 3)) = v8;
        }
    }
}

// ---------------- launch ----------------
extern "C" void kernel_launch(void* const* d_in, const int* in_sizes, int n_in,
                              void* d_out, int out_size) {
    const float* x      = (const float*)d_in[0];
    const float* log_dt = (const float*)d_in[1];
    const float* A_re   = (const float*)d_in[2];
    const float* A_im   = (const float*)d_in[3];
    const float* C_re   = (const float*)d_in[4];
    const float* C_im   = (const float*)d_in[5];
    const float* D      = (const float*)d_in[6];
    const float* W      = (const float*)d_in[7];
    const float* bias   = (const float*)d_in[8];
    float* out = (float*)d_out;

    prep_emb_kernel<<<(3*16*CH3 + 255)/256, 256>>>();
    prep_ct_kernel<<<(Hc*Nst + 255)/256, 256>>>(log_dt, A_re, A_im, C_re, C_im);
    v_kernel<<<(BSz*Hc*Lt/2 + 255)/256, 256>>>(x);
    ssmA_kernel<<<BSz*Hc*NCH, 32>>>();
    ssmB_kernel<<<BSz*Hc, 32>>>();
    ssmC_kernel<<<BSz*Hc*NCH, 32>>>(D);
    gemm_kernel<<<dim3(Lt/128, OUTc/64, BSz), 128>>>(W, bias, out);
}

// round 6
// speedup vs baseline: 1.6023x; 1.0467x over previous
#include <cuda_runtime.h>
#include <math.h>
#include <stdint.h>

#define Hc   1024
#define Nst  64
#define Lt   4096
#define OUTc 512
#define BSz  2
#define CH3  342   // per-axis posenc channels
#define Tc   512   // chunk length
#define NCH  8     // Lt / Tc

typedef unsigned long long u64;

// ---------------- f32x2 packed math (sm_103a FFMA2 path) ----------------
__device__ __forceinline__ u64 f2fma(u64 a, u64 b, u64 c) {
    u64 d; asm("fma.rn.f32x2 %0,%1,%2,%3;" : "=l"(d) : "l"(a), "l"(b), "l"(c)); return d;
}
__device__ __forceinline__ u64 f2mul(u64 a, u64 b) {
    u64 d; asm("mul.rn.f32x2 %0,%1,%2;" : "=l"(d) : "l"(a), "l"(b)); return d;
}
__device__ __forceinline__ u64 f2add(u64 a, u64 b) {
    u64 d; asm("add.rn.f32x2 %0,%1,%2;" : "=l"(d) : "l"(a), "l"(b)); return d;
}
__device__ __forceinline__ u64 f2pack(float lo, float hi) {
    u64 d; asm("mov.b64 %0,{%1,%2};" : "=l"(d) : "f"(lo), "f"(hi)); return d;
}
__device__ __forceinline__ u64 f2dup(float v) {
    u64 d; asm("mov.b64 %0,{%1,%1};" : "=l"(d) : "f"(v)); return d;
}
__device__ __forceinline__ float2 f2unpack(u64 v) {
    float2 r; asm("mov.b64 {%0,%1},%2;" : "=f"(r.x), "=f"(r.y) : "l"(v)); return r;
}
__device__ __forceinline__ float tf32rna(float v) {
    uint32_t u; asm("cvt.rna.tf32.f32 %0, %1;" : "=r"(u) : "f"(v));
    return __uint_as_float(u);
}

// ---------------- scratch ----------------
__device__ float g_v [BSz*Hc*Lt];     // v = x + pe, layout (b, c, l)
__device__ float g_yT[BSz*Hc*Lt];     // gelu(conv + D*v), tf32-rounded, (b, c, l)
__device__ float g_Wt[Hc*OUTc];       // W pre-rounded to tf32
__device__ float g_wre[Hc*Nst],  g_wim[Hc*Nst];
__device__ float g_w2re[Hc*Nst], g_w2im[Hc*Nst];   // w^2
__device__ float g_wTre[Hc*Nst], g_wTim[Hc*Nst];   // w^Tc
__device__ float g_ctre[Hc*Nst], g_ctim[Hc*Nst];
__device__ float g_emb[3*16*CH3];     // [axis][pos][k]
__device__ u64 g_csr[BSz*Hc*NCH*32], g_csi[BSz*Hc*NCH*32];  // chunk contributions
__device__ u64 g_s0r[BSz*Hc*NCH*32], g_s0i[BSz*Hc*NCH*32];  // chunk start states

// ---------------- posenc tables ----------------
__global__ void prep_emb_kernel() {
    int idx = blockIdx.x * blockDim.x + threadIdx.x;
    if (idx >= 3*16*CH3) return;
    int k   = idx % CH3;
    int pos = (idx / CH3) % 16;
    int i   = k >> 1;
    float freq = expf(-logf(10000.0f) * (float)(2*i) / (float)CH3);
    float arg  = (float)pos * freq;
    g_emb[idx] = (k & 1) ? cosf(arg) : sinf(arg);
}

// ---------------- W -> tf32 (round-to-nearest) ----------------
__global__ void prep_wt_kernel(const float* __restrict__ W) {
    int i4 = blockIdx.x * blockDim.x + threadIdx.x;
    if (i4 >= Hc*OUTc/4) return;
    float4 w = ((const float4*)W)[i4];
    ((float4*)g_Wt)[i4] = make_float4(tf32rna(w.x), tf32rna(w.y), tf32rna(w.z), tf32rna(w.w));
}

// ---------------- discretize (double precision for w^2 / w^Tc accuracy) ----------------
__global__ void prep_ct_kernel(const float* __restrict__ log_dt,
                               const float* __restrict__ Are, const float* __restrict__ Aim,
                               const float* __restrict__ Cre, const float* __restrict__ Cim) {
    int idx = blockIdx.x * blockDim.x + threadIdx.x;
    if (idx >= Hc*Nst) return;
    int c = idx >> 6;
    double dt  = exp((double)log_dt[c]);
    double ar  = (double)Are[idx], ai = (double)Aim[idx];
    double dar = dt*ar, dai = dt*ai;
    double er  = exp(dar);
    double sn  = sin(dai), cs = cos(dai);
    double wr = er*cs, wi = er*sn;
    g_wre[idx] = (float)wr; g_wim[idx] = (float)wi;
    double er2 = exp(2.0*dar);
    g_w2re[idx] = (float)(er2*cos(2.0*dai)); g_w2im[idx] = (float)(er2*sin(2.0*dai));
    double erT = exp((double)Tc * dar);
    g_wTre[idx] = (float)(erT*cos((double)Tc*dai)); g_wTim[idx] = (float)(erT*sin((double)Tc*dai));
    double nr = wr - 1.0, ni = wi;
    double inv = 1.0 / (ar*ar + ai*ai);
    double qr = (nr*ar + ni*ai) * inv;
    double qi = (ni*ar - nr*ai) * inv;
    double cr = (double)Cre[idx], ci = (double)Cim[idx];
    g_ctre[idx] = (float)(2.0*(cr*qr - ci*qi));
    g_ctim[idx] = (float)(2.0*(cr*qi + ci*qr));
}

// ---------------- v = x + posenc ----------------
__global__ void v_kernel(const float* __restrict__ x) {
    int i4 = blockIdx.x * blockDim.x + threadIdx.x;
    if (i4 >= BSz*Hc*Lt/4) return;
    int l4 = i4 & (Lt/4 - 1);
    int c  = (i4 >> 10) & (Hc - 1);
    int l  = l4 << 2;
    int lw = l & 15, lh = (l >> 4) & 15, lf = l >> 8;
    float4 xv = ((const float4*)x)[i4];
    float4 pv;
    if (c < CH3) {
        float e = g_emb[lf*CH3 + c];
        pv = make_float4(e, e, e, e);
    } else if (c < 2*CH3) {
        float e = g_emb[(16 + lh)*CH3 + (c - CH3)];
        pv = make_float4(e, e, e, e);
    } else {
        int k = c - 2*CH3;
        const float* ez = g_emb + 32*CH3 + k;
        pv = make_float4(ez[(lw+0)*CH3], ez[(lw+1)*CH3], ez[(lw+2)*CH3], ez[(lw+3)*CH3]);
    }
    ((float4*)g_v)[i4] = make_float4(xv.x+pv.x, xv.y+pv.y, xv.z+pv.z, xv.w+pv.w);
}

// ---------------- pass A: per-chunk recurrence from zero -> B_k (decim-by-2) ----------------
// 4 warps per block, one chunk per warp
__global__ __launch_bounds__(128) void ssmA_kernel() {
    int gid  = blockIdx.x * 4 + (threadIdx.x >> 5);   // (b*Hc+c)*NCH + k
    int lane = threadIdx.x & 31;
    int wid  = gid >> 3, k = gid & (NCH - 1);
    int c    = wid & (Hc - 1);
    int n0   = (c << 6) + lane;

    u64 Wr   = f2pack( g_wre[n0],   g_wre[n0+32]);
    u64 Wi   = f2pack( g_wim[n0],   g_wim[n0+32]);
    u64 W2r  = f2pack( g_w2re[n0],  g_w2re[n0+32]);
    u64 W2i  = f2pack( g_w2im[n0],  g_w2im[n0+32]);
    u64 W2in = f2pack(-g_w2im[n0], -g_w2im[n0+32]);

    const float4* vp = (const float4*)(g_v + (size_t)wid * Lt + k * Tc);
    u64 Sr = 0ull, Si = 0ull;

    for (int it = 0; it < Tc/8; ++it) {
        float4 a = vp[it*2], b = vp[it*2 + 1];
        #pragma unroll
        for (int g = 0; g < 4; ++g) {
            float v0 = (g==0)?a.x:(g==1)?a.z:(g==2)?b.x:b.z;
            float v1 = (g==0)?a.y:(g==1)?a.w:(g==2)?b.y:b.w;
            u64 v02 = f2dup(v0), v12 = f2dup(v1);
            // two steps: s = w2*s + (w*v0 + v1)
            u64 ir  = f2fma(Wr, v02, v12);
            u64 ii  = f2mul(Wi, v02);
            u64 tr  = f2fma(W2in, Si, ir);
            u64 nSr = f2fma(W2r,  Sr, tr);
            u64 ti  = f2fma(W2r,  Si, ii);
            Si      = f2fma(W2i,  Sr, ti);
            Sr      = nSr;
        }
    }
    g_csr[gid*32 + lane] = Sr;
    g_csi[gid*32 + lane] = Si;
}

// ---------------- pass B: scan chunk-start states ----------------
__global__ __launch_bounds__(32) void ssmB_kernel() {
    int wid  = blockIdx.x;               // b*Hc + c
    int lane = threadIdx.x;
    int c    = wid & (Hc - 1);
    int n0   = (c << 6) + lane;

    u64 WTr  = f2pack( g_wTre[n0],  g_wTre[n0+32]);
    u64 WTi  = f2pack( g_wTim[n0],  g_wTim[n0+32]);
    u64 WTin = f2pack(-g_wTim[n0], -g_wTim[n0+32]);

    u64 sr = 0ull, si = 0ull;
    #pragma unroll
    for (int k = 0; k < NCH; ++k) {
        int idx = (wid*NCH + k)*32 + lane;
        g_s0r[idx] = sr; g_s0i[idx] = si;
        u64 br = g_csr[idx], bi = g_csi[idx];
        u64 t  = f2fma(WTin, si, br);
        u64 u  = f2fma(WTr,  si, bi);
        u64 ns = f2fma(WTr,  sr, t);
        si     = f2fma(WTi,  sr, u);
        sr     = ns;
    }
}

// ---------------- pass C: recurrence with init state + dot + skip + gelu ----------------
// 4 warps per block, one chunk per warp
#define RP2 36   // words per reduce row (32 floats + 4 pad)

__global__ __launch_bounds__(128) void ssmC_kernel(const float* __restrict__ D) {
    __shared__ float ps[4][32*RP2];
    int wrp  = threadIdx.x >> 5;
    int gid  = blockIdx.x * 4 + wrp;     // (b*Hc+c)*NCH + k
    int lane = threadIdx.x & 31;
    int wid  = gid >> 3, k = gid & (NCH - 1);
    int c    = wid & (Hc - 1);
    int n0   = (c << 6) + lane;

    u64 Wr  = f2pack( g_wre[n0],   g_wre[n0+32]);
    u64 Wi  = f2pack( g_wim[n0],   g_wim[n0+32]);
    u64 Win = f2pack(-g_wim[n0],  -g_wim[n0+32]);
    u64 Cr  = f2pack( g_ctre[n0],  g_ctre[n0+32]);
    u64 Cin = f2pack(-g_ctim[n0], -g_ctim[n0+32]);
    float dc = D[c];

    const float4* vp = (const float4*)(g_v + (size_t)wid * Lt + k * Tc);
    const float*  vs = g_v + (size_t)wid * Lt + k * Tc;
    float*        yp = g_yT + (size_t)wid * Lt + k * Tc;
    float*        myps = ps[wrp];

    u64 Sr = g_s0r[gid*32 + lane];
    u64 Si = g_s0i[gid*32 + lane];

    for (int base = 0; base < Tc; base += 32) {
        #pragma unroll
        for (int h = 0; h < 4; ++h) {
            float4 a = vp[(base >> 2) + h*2], bq = vp[(base >> 2) + h*2 + 1];
            #pragma unroll
            for (int j = 0; j < 8; ++j) {
                float vvf = (j==0)?a.x:(j==1)?a.y:(j==2)?a.z:(j==3)?a.w:
                            (j==4)?bq.x:(j==5)?bq.y:(j==6)?bq.z:bq.w;
                u64 vv = f2dup(vvf);
                u64 t = f2fma(Win, Si, vv); u64 u = f2mul(Wr, Si);
                u64 n = f2fma(Wr, Sr, t); Si = f2fma(Wi, Sr, u); Sr = n;
                float2 pf = f2unpack(f2fma(Cin, Si, f2mul(Cr, Sr)));
                myps[(h*8 + j)*RP2 + lane] = pf.x + pf.y;
            }
        }
        __syncwarp();
        // lane t reduces row t (timestep base+t): 8x LDS.128, packed adds
        const ulonglong2* row = (const ulonglong2*)&myps[lane * RP2];
        u64 a0 = 0ull, a1 = 0ull;
        #pragma unroll
        for (int q = 0; q < 8; ++q) {
            ulonglong2 rr = row[q];
            a0 = f2add(a0, rr.x);
            a1 = f2add(a1, rr.y);
        }
        float2 sf = f2unpack(f2add(a0, a1));
        float vvl = vs[base + lane];
        float s   = sf.x + sf.y + dc * vvl;   // + D*v skip (deferred)
        float a2 = 1.5957691216057308f * fmaf(0.044715f * s, s * s, s);
        float e  = __expf(a2);
        float th = 1.0f - __fdividef(2.0f, e + 1.0f);
        yp[base + lane] = tf32rna(0.5f * s * (1.0f + th));   // round for exact tf32 GEMM
        __syncwarp();
    }
}

// ---------------- tf32 tensor-core GEMM ----------------
// out[b,o,l] = sum_k Wt[k,o] * yT[b,k,l] + bias[o]
// tile: 64(o=M) x 128(l=N), BK=8, 128 threads = 4 warps, warp tile 32x64
__global__ __launch_bounds__(128) void gemm_kernel(const float* __restrict__ bias,
                                                   float* __restrict__ out) {
    __shared__ float Ws[2][8][68];    // [k][o]
    __shared__ float Ys[2][8][132];   // [k][l]
    int b  = blockIdx.z;
    int oo = blockIdx.y << 6;
    int ll = blockIdx.x << 7;
    int t  = threadIdx.x;
    int lane = t & 31, wid = t >> 5;
    int om = (wid & 1) << 5;
    int on = (wid >> 1) << 6;
    int gID = lane >> 2, tig = lane & 3;

    int wr_ = t >> 4;                 // 0..7
    int wc  = (t & 15) << 2;
    int yc  = (t & 15) << 3;
    const float* Wp = g_Wt + (size_t)wr_ * OUTc + oo + wc;
    const float* Yp = g_yT + ((size_t)b * Hc + wr_) * Lt + ll + yc;

    float4 wv  = *(const float4*)Wp;
    float4 yv0 = *(const float4*)Yp;
    float4 yv1 = *(const float4*)(Yp + 4);

    float acc[2][8][4];
    #pragma unroll
    for (int mt = 0; mt < 2; ++mt)
        #pragma unroll
        for (int nt = 0; nt < 8; ++nt)
            #pragma unroll
            for (int r = 0; r < 4; ++r) acc[mt][nt][r] = 0.f;

    int buf = 0;
    for (int s = 0; s < Hc/8; ++s) {
        *(float4*)&Ws[buf][wr_][wc]     = wv;
        *(float4*)&Ys[buf][wr_][yc]     = yv0;
        *(float4*)&Ys[buf][wr_][yc + 4] = yv1;
        __syncthreads();
        if (s + 1 < Hc/8) {
            size_t ko = (size_t)(s + 1) * 8;
            wv  = *(const float4*)(Wp + ko * OUTc);
            yv0 = *(const float4*)(Yp + ko * Lt);
            yv1 = *(const float4*)(Yp + ko * Lt + 4);
        }
        uint32_t a[2][4];
        #pragma unroll
        for (int mt = 0; mt < 2; ++mt) {
            int r0 = om + (mt << 4) + gID;
            a[mt][0] = __float_as_uint(Ws[buf][tig    ][r0]);
            a[mt][1] = __float_as_uint(Ws[buf][tig    ][r0 + 8]);
            a[mt][2] = __float_as_uint(Ws[buf][tig + 4][r0]);
            a[mt][3] = __float_as_uint(Ws[buf][tig + 4][r0 + 8]);
        }
        uint32_t bf[8][2];
        #pragma unroll
        for (int nt = 0; nt < 8; ++nt) {
            int cn = on + (nt << 3) + gID;
            bf[nt][0] = __float_as_uint(Ys[buf][tig    ][cn]);
            bf[nt][1] = __float_as_uint(Ys[buf][tig + 4][cn]);
        }
        #pragma unroll
        for (int mt = 0; mt < 2; ++mt)
            #pragma unroll
            for (int nt = 0; nt < 8; ++nt) {
                asm("mma.sync.aligned.m16n8k8.row.col.f32.tf32.tf32.f32 "
                    "{%0,%1,%2,%3},{%4,%5,%6,%7},{%8,%9},{%0,%1,%2,%3};"
                    : "+f"(acc[mt][nt][0]), "+f"(acc[mt][nt][1]),
                      "+f"(acc[mt][nt][2]), "+f"(acc[mt][nt][3])
                    : "r"(a[mt][0]), "r"(a[mt][1]), "r"(a[mt][2]), "r"(a[mt][3]),
                      "r"(bf[nt][0]), "r"(bf[nt][1]));
            }
        buf ^= 1;
    }

    #pragma unroll
    for (int mt = 0; mt < 2; ++mt) {
        int o0 = oo + om + (mt << 4) + gID;
        float b0 = __ldg(&bias[o0]);
        float b8 = __ldg(&bias[o0 + 8]);
        float* r0p = out + ((size_t)b * OUTc + o0)     * Lt + ll + on + (tig << 1);
        float* r8p = out + ((size_t)b * OUTc + o0 + 8) * Lt + ll + on + (tig << 1);
        #pragma unroll
        for (int nt = 0; nt < 8; ++nt) {
            *(float2*)(r0p + (nt << 3)) = make_float2(acc[mt][nt][0] + b0, acc[mt][nt][1] + b0);
            *(float2*)(r8p + (nt << 3)) = make_float2(acc[mt][nt][2] + b8, acc[mt][nt][3] + b8);
        }
    }
}

// ---------------- launch ----------------
extern "C" void kernel_launch(void* const* d_in, const int* in_sizes, int n_in,
                              void* d_out, int out_size) {
    const float* x      = (const float*)d_in[0];
    const float* log_dt = (const float*)d_in[1];
    const float* A_re   = (const float*)d_in[2];
    const float* A_im   = (const float*)d_in[3];
    const float* C_re   = (const float*)d_in[4];
    const float* C_im   = (const float*)d_in[5];
    const float* D      = (const float*)d_in[6];
    const float* W      = (const float*)d_in[7];
    const float* bias   = (const float*)d_in[8];
    float* out = (float*)d_out;

    prep_emb_kernel<<<(3*16*CH3 + 255)/256, 256>>>();
    prep_ct_kernel<<<(Hc*Nst + 255)/256, 256>>>(log_dt, A_re, A_im, C_re, C_im);
    prep_wt_kernel<<<(Hc*OUTc/4 + 255)/256, 256>>>(W);
    v_kernel<<<(BSz*Hc*Lt/4 + 255)/256, 256>>>(x);
    ssmA_kernel<<<BSz*Hc*NCH/4, 128>>>();
    ssmB_kernel<<<BSz*Hc, 32>>>();
    ssmC_kernel<<<BSz*Hc*NCH/4, 128>>>(D);
    gemm_kernel<<<dim3(Lt/128, OUTc/64, BSz), 128>>>(bias, out);
}

// round 7
// speedup vs baseline: 1.6047x; 1.0015x over previous
#include <cuda_runtime.h>
#include <math.h>
#include <stdint.h>

#define Hc   1024
#define Nst  64
#define Lt   4096
#define OUTc 512
#define BSz  2
#define CH3  342   // per-axis posenc channels
#define Tc   512   // chunk length
#define NCH  8     // Lt / Tc

typedef unsigned long long u64;

// ---------------- f32x2 packed math (sm_103a FFMA2 path) ----------------
__device__ __forceinline__ u64 f2fma(u64 a, u64 b, u64 c) {
    u64 d; asm("fma.rn.f32x2 %0,%1,%2,%3;" : "=l"(d) : "l"(a), "l"(b), "l"(c)); return d;
}
__device__ __forceinline__ u64 f2mul(u64 a, u64 b) {
    u64 d; asm("mul.rn.f32x2 %0,%1,%2;" : "=l"(d) : "l"(a), "l"(b)); return d;
}
__device__ __forceinline__ u64 f2add(u64 a, u64 b) {
    u64 d; asm("add.rn.f32x2 %0,%1,%2;" : "=l"(d) : "l"(a), "l"(b)); return d;
}
__device__ __forceinline__ u64 f2pack(float lo, float hi) {
    u64 d; asm("mov.b64 %0,{%1,%2};" : "=l"(d) : "f"(lo), "f"(hi)); return d;
}
__device__ __forceinline__ u64 f2dup(float v) {
    u64 d; asm("mov.b64 %0,{%1,%1};" : "=l"(d) : "f"(v)); return d;
}
__device__ __forceinline__ float2 f2unpack(u64 v) {
    float2 r; asm("mov.b64 {%0,%1},%2;" : "=f"(r.x), "=f"(r.y) : "l"(v)); return r;
}
__device__ __forceinline__ float tf32rna(float v) {
    uint32_t u; asm("cvt.rna.tf32.f32 %0, %1;" : "=r"(u) : "f"(v));
    return __uint_as_float(u);
}

// ---------------- scratch ----------------
__device__ float g_v [BSz*Hc*Lt];     // v = x + pe, layout (b, c, l)
__device__ float g_yT[BSz*Hc*Lt];     // gelu(conv + D*v), tf32-rounded, (b, c, l)
__device__ float g_Wt[Hc*OUTc];       // W pre-rounded to tf32
__device__ float g_wre[Hc*Nst],  g_wim[Hc*Nst];
__device__ float g_w2re[Hc*Nst], g_w2im[Hc*Nst];   // w^2
__device__ float g_wTre[Hc*Nst], g_wTim[Hc*Nst];   // w^Tc
__device__ float g_ctre[Hc*Nst], g_ctim[Hc*Nst];
__device__ float g_emb[3*16*CH3];     // [axis][pos][k]
__device__ u64 g_csr[BSz*Hc*NCH*32], g_csi[BSz*Hc*NCH*32];  // chunk contributions
__device__ u64 g_s0r[BSz*Hc*NCH*32], g_s0i[BSz*Hc*NCH*32];  // chunk start states

// ---------------- posenc tables ----------------
__global__ void prep_emb_kernel() {
    int idx = blockIdx.x * blockDim.x + threadIdx.x;
    if (idx >= 3*16*CH3) return;
    int k   = idx % CH3;
    int pos = (idx / CH3) % 16;
    int i   = k >> 1;
    float freq = expf(-logf(10000.0f) * (float)(2*i) / (float)CH3);
    float arg  = (float)pos * freq;
    g_emb[idx] = (k & 1) ? cosf(arg) : sinf(arg);
}

// ---------------- W -> tf32 (round-to-nearest) ----------------
__global__ void prep_wt_kernel(const float* __restrict__ W) {
    int i4 = blockIdx.x * blockDim.x + threadIdx.x;
    if (i4 >= Hc*OUTc/4) return;
    float4 w = ((const float4*)W)[i4];
    ((float4*)g_Wt)[i4] = make_float4(tf32rna(w.x), tf32rna(w.y), tf32rna(w.z), tf32rna(w.w));
}

// ---------------- discretize (double precision for w^2 / w^Tc accuracy) ----------------
__global__ void prep_ct_kernel(const float* __restrict__ log_dt,
                               const float* __restrict__ Are, const float* __restrict__ Aim,
                               const float* __restrict__ Cre, const float* __restrict__ Cim) {
    int idx = blockIdx.x * blockDim.x + threadIdx.x;
    if (idx >= Hc*Nst) return;
    int c = idx >> 6;
    double dt  = exp((double)log_dt[c]);
    double ar  = (double)Are[idx], ai = (double)Aim[idx];
    double dar = dt*ar, dai = dt*ai;
    double er  = exp(dar);
    double sn  = sin(dai), cs = cos(dai);
    double wr = er*cs, wi = er*sn;
    g_wre[idx] = (float)wr; g_wim[idx] = (float)wi;
    double er2 = exp(2.0*dar);
    g_w2re[idx] = (float)(er2*cos(2.0*dai)); g_w2im[idx] = (float)(er2*sin(2.0*dai));
    double erT = exp((double)Tc * dar);
    g_wTre[idx] = (float)(erT*cos((double)Tc*dai)); g_wTim[idx] = (float)(erT*sin((double)Tc*dai));
    double nr = wr - 1.0, ni = wi;
    double inv = 1.0 / (ar*ar + ai*ai);
    double qr = (nr*ar + ni*ai) * inv;
    double qi = (ni*ar - nr*ai) * inv;
    double cr = (double)Cre[idx], ci = (double)Cim[idx];
    g_ctre[idx] = (float)(2.0*(cr*qr - ci*qi));
    g_ctim[idx] = (float)(2.0*(cr*qi + ci*qr));
}

// ---------------- v = x + posenc ----------------
__global__ void v_kernel(const float* __restrict__ x) {
    int i4 = blockIdx.x * blockDim.x + threadIdx.x;
    if (i4 >= BSz*Hc*Lt/4) return;
    int l4 = i4 & (Lt/4 - 1);
    int c  = (i4 >> 10) & (Hc - 1);
    int l  = l4 << 2;
    int lw = l & 15, lh = (l >> 4) & 15, lf = l >> 8;
    float4 xv = ((const float4*)x)[i4];
    float4 pv;
    if (c < CH3) {
        float e = g_emb[lf*CH3 + c];
        pv = make_float4(e, e, e, e);
    } else if (c < 2*CH3) {
        float e = g_emb[(16 + lh)*CH3 + (c - CH3)];
        pv = make_float4(e, e, e, e);
    } else {
        int k = c - 2*CH3;
        const float* ez = g_emb + 32*CH3 + k;
        pv = make_float4(ez[(lw+0)*CH3], ez[(lw+1)*CH3], ez[(lw+2)*CH3], ez[(lw+3)*CH3]);
    }
    ((float4*)g_v)[i4] = make_float4(xv.x+pv.x, xv.y+pv.y, xv.z+pv.z, xv.w+pv.w);
}

// ---------------- pass A: per-chunk recurrence from zero -> B_k (decim-by-2) ----------------
// 4 warps per block, one chunk per warp
__global__ __launch_bounds__(128) void ssmA_kernel() {
    int gid  = blockIdx.x * 4 + (threadIdx.x >> 5);   // (b*Hc+c)*NCH + k
    int lane = threadIdx.x & 31;
    int wid  = gid >> 3, k = gid & (NCH - 1);
    int c    = wid & (Hc - 1);
    int n0   = (c << 6) + lane;

    u64 Wr   = f2pack( g_wre[n0],   g_wre[n0+32]);
    u64 Wi   = f2pack( g_wim[n0],   g_wim[n0+32]);
    u64 W2r  = f2pack( g_w2re[n0],  g_w2re[n0+32]);
    u64 W2i  = f2pack( g_w2im[n0],  g_w2im[n0+32]);
    u64 W2in = f2pack(-g_w2im[n0], -g_w2im[n0+32]);

    const float4* vp = (const float4*)(g_v + (size_t)wid * Lt + k * Tc);
    u64 Sr = 0ull, Si = 0ull;

    for (int it = 0; it < Tc/8; ++it) {
        float4 a = vp[it*2], b = vp[it*2 + 1];
        #pragma unroll
        for (int g = 0; g < 4; ++g) {
            float v0 = (g==0)?a.x:(g==1)?a.z:(g==2)?b.x:b.z;
            float v1 = (g==0)?a.y:(g==1)?a.w:(g==2)?b.y:b.w;
            u64 v02 = f2dup(v0), v12 = f2dup(v1);
            // two steps: s = w2*s + (w*v0 + v1)
            u64 ir  = f2fma(Wr, v02, v12);
            u64 ii  = f2mul(Wi, v02);
            u64 tr  = f2fma(W2in, Si, ir);
            u64 nSr = f2fma(W2r,  Sr, tr);
            u64 ti  = f2fma(W2r,  Si, ii);
            Si      = f2fma(W2i,  Sr, ti);
            Sr      = nSr;
        }
    }
    g_csr[gid*32 + lane] = Sr;
    g_csi[gid*32 + lane] = Si;
}

// ---------------- pass B: scan chunk-start states ----------------
__global__ __launch_bounds__(32) void ssmB_kernel() {
    int wid  = blockIdx.x;               // b*Hc + c
    int lane = threadIdx.x;
    int c    = wid & (Hc - 1);
    int n0   = (c << 6) + lane;

    u64 WTr  = f2pack( g_wTre[n0],  g_wTre[n0+32]);
    u64 WTi  = f2pack( g_wTim[n0],  g_wTim[n0+32]);
    u64 WTin = f2pack(-g_wTim[n0], -g_wTim[n0+32]);

    u64 sr = 0ull, si = 0ull;
    #pragma unroll
    for (int k = 0; k < NCH; ++k) {
        int idx = (wid*NCH + k)*32 + lane;
        g_s0r[idx] = sr; g_s0i[idx] = si;
        u64 br = g_csr[idx], bi = g_csi[idx];
        u64 t  = f2fma(WTin, si, br);
        u64 u  = f2fma(WTr,  si, bi);
        u64 ns = f2fma(WTr,  sr, t);
        si     = f2fma(WTi,  sr, u);
        sr     = ns;
    }
}

// ---------------- pass C: recurrence with init state + dot + skip + gelu ----------------
// 4 warps per block, one chunk per warp
#define RP2 36   // words per reduce row (32 floats + 4 pad)

__global__ __launch_bounds__(128) void ssmC_kernel(const float* __restrict__ D) {
    __shared__ float ps[4][32*RP2];
    int wrp  = threadIdx.x >> 5;
    int gid  = blockIdx.x * 4 + wrp;     // (b*Hc+c)*NCH + k
    int lane = threadIdx.x & 31;
    int wid  = gid >> 3, k = gid & (NCH - 1);
    int c    = wid & (Hc - 1);
    int n0   = (c << 6) + lane;

    u64 Wr  = f2pack( g_wre[n0],   g_wre[n0+32]);
    u64 Wi  = f2pack( g_wim[n0],   g_wim[n0+32]);
    u64 Win = f2pack(-g_wim[n0],  -g_wim[n0+32]);
    u64 Cr  = f2pack( g_ctre[n0],  g_ctre[n0+32]);
    u64 Cin = f2pack(-g_ctim[n0], -g_ctim[n0+32]);
    float dc = D[c];

    const float4* vp = (const float4*)(g_v + (size_t)wid * Lt + k * Tc);
    const float*  vs = g_v + (size_t)wid * Lt + k * Tc;
    float*        yp = g_yT + (size_t)wid * Lt + k * Tc;
    float*        myps = ps[wrp];

    u64 Sr = g_s0r[gid*32 + lane];
    u64 Si = g_s0i[gid*32 + lane];

    for (int base = 0; base < Tc; base += 32) {
        #pragma unroll
        for (int h = 0; h < 4; ++h) {
            float4 a = vp[(base >> 2) + h*2], bq = vp[(base >> 2) + h*2 + 1];
            #pragma unroll
            for (int j = 0; j < 8; ++j) {
                float vvf = (j==0)?a.x:(j==1)?a.y:(j==2)?a.z:(j==3)?a.w:
                            (j==4)?bq.x:(j==5)?bq.y:(j==6)?bq.z:bq.w;
                u64 vv = f2dup(vvf);
                u64 t = f2fma(Win, Si, vv); u64 u = f2mul(Wr, Si);
                u64 n = f2fma(Wr, Sr, t); Si = f2fma(Wi, Sr, u); Sr = n;
                float2 pf = f2unpack(f2fma(Cin, Si, f2mul(Cr, Sr)));
                myps[(h*8 + j)*RP2 + lane] = pf.x + pf.y;
            }
        }
        __syncwarp();
        // lane t reduces row t (timestep base+t): 8x LDS.128, packed adds
        const ulonglong2* row = (const ulonglong2*)&myps[lane * RP2];
        u64 a0 = 0ull, a1 = 0ull;
        #pragma unroll
        for (int q = 0; q < 8; ++q) {
            ulonglong2 rr = row[q];
            a0 = f2add(a0, rr.x);
            a1 = f2add(a1, rr.y);
        }
        float2 sf = f2unpack(f2add(a0, a1));
        float vvl = vs[base + lane];
        float s   = sf.x + sf.y + dc * vvl;   // + D*v skip (deferred)
        float a2 = 1.5957691216057308f * fmaf(0.044715f * s, s * s, s);
        float e  = __expf(a2);
        float th = 1.0f - __fdividef(2.0f, e + 1.0f);
        yp[base + lane] = tf32rna(0.5f * s * (1.0f + th));   // round for exact tf32 GEMM
        __syncwarp();
    }
}

// ---------------- tf32 tensor-core GEMM ----------------
// out[b,o,l] = sum_k Wt[k,o] * yT[b,k,l] + bias[o]
// tile: 64(o=M) x 128(l=N), BK=8, 128 threads = 4 warps, warp tile 32x64
__global__ __launch_bounds__(128) void gemm_kernel(const float* __restrict__ bias,
                                                   float* __restrict__ out) {
    __shared__ float Ws[2][8][68];    // [k][o]
    __shared__ float Ys[2][8][132];   // [k][l]
    int b  = blockIdx.z;
    int oo = blockIdx.y << 6;
    int ll = blockIdx.x << 7;
    int t  = threadIdx.x;
    int lane = t & 31, wid = t >> 5;
    int om = (wid & 1) << 5;
    int on = (wid >> 1) << 6;
    int gID = lane >> 2, tig = lane & 3;

    int wr_ = t >> 4;                 // 0..7
    int wc  = (t & 15) << 2;
    int yc  = (t & 15) << 3;
    const float* Wp = g_Wt + (size_t)wr_ * OUTc + oo + wc;
    const float* Yp = g_yT + ((size_t)b * Hc + wr_) * Lt + ll + yc;

    float4 wv  = *(const float4*)Wp;
    float4 yv0 = *(const float4*)Yp;
    float4 yv1 = *(const float4*)(Yp + 4);

    float acc[2][8][4];
    #pragma unroll
    for (int mt = 0; mt < 2; ++mt)
        #pragma unroll
        for (int nt = 0; nt < 8; ++nt)
            #pragma unroll
            for (int r = 0; r < 4; ++r) acc[mt][nt][r] = 0.f;

    int buf = 0;
    for (int s = 0; s < Hc/8; ++s) {
        *(float4*)&Ws[buf][wr_][wc]     = wv;
        *(float4*)&Ys[buf][wr_][yc]     = yv0;
        *(float4*)&Ys[buf][wr_][yc + 4] = yv1;
        __syncthreads();
        if (s + 1 < Hc/8) {
            size_t ko = (size_t)(s + 1) * 8;
            wv  = *(const float4*)(Wp + ko * OUTc);
            yv0 = *(const float4*)(Yp + ko * Lt);
            yv1 = *(const float4*)(Yp + ko * Lt + 4);
        }
        uint32_t a[2][4];
        #pragma unroll
        for (int mt = 0; mt < 2; ++mt) {
            int r0 = om + (mt << 4) + gID;
            a[mt][0] = __float_as_uint(Ws[buf][tig    ][r0]);
            a[mt][1] = __float_as_uint(Ws[buf][tig    ][r0 + 8]);
            a[mt][2] = __float_as_uint(Ws[buf][tig + 4][r0]);
            a[mt][3] = __float_as_uint(Ws[buf][tig + 4][r0 + 8]);
        }
        uint32_t bf[8][2];
        #pragma unroll
        for (int nt = 0; nt < 8; ++nt) {
            int cn = on + (nt << 3) + gID;
            bf[nt][0] = __float_as_uint(Ys[buf][tig    ][cn]);
            bf[nt][1] = __float_as_uint(Ys[buf][tig + 4][cn]);
        }
        #pragma unroll
        for (int mt = 0; mt < 2; ++mt)
            #pragma unroll
            for (int nt = 0; nt < 8; ++nt) {
                asm("mma.sync.aligned.m16n8k8.row.col.f32.tf32.tf32.f32 "
                    "{%0,%1,%2,%3},{%4,%5,%6,%7},{%8,%9},{%0,%1,%2,%3};"
                    : "+f"(acc[mt][nt][0]), "+f"(acc[mt][nt][1]),
                      "+f"(acc[mt][nt][2]), "+f"(acc[mt][nt][3])
                    : "r"(a[mt][0]), "r"(a[mt][1]), "r"(a[mt][2]), "r"(a[mt][3]),
                      "r"(bf[nt][0]), "r"(bf[nt][1]));
            }
        buf ^= 1;
    }

    #pragma unroll
    for (int mt = 0; mt < 2; ++mt) {
        int o0 = oo + om + (mt << 4) + gID;
        float b0 = __ldg(&bias[o0]);
        float b8 = __ldg(&bias[o0 + 8]);
        float* r0p = out + ((size_t)b * OUTc + o0)     * Lt + ll + on + (tig << 1);
        float* r8p = out + ((size_t)b * OUTc + o0 + 8) * Lt + ll + on + (tig << 1);
        #pragma unroll
        for (int nt = 0; nt < 8; ++nt) {
            *(float2*)(r0p + (nt << 3)) = make_float2(acc[mt][nt][0] + b0, acc[mt][nt][1] + b0);
            *(float2*)(r8p + (nt << 3)) = make_float2(acc[mt][nt][2] + b8, acc[mt][nt][3] + b8);
        }
    }
}

// ---------------- launch ----------------
extern "C" void kernel_launch(void* const* d_in, const int* in_sizes, int n_in,
                              void* d_out, int out_size) {
    const float* x      = (const float*)d_in[0];
    const float* log_dt = (const float*)d_in[1];
    const float* A_re   = (const float*)d_in[2];
    const float* A_im   = (const float*)d_in[3];
    const float* C_re   = (const float*)d_in[4];
    const float* C_im   = (const float*)d_in[5];
    const float* D      = (const float*)d_in[6];
    const float* W      = (const float*)d_in[7];
    const float* bias   = (const float*)d_in[8];
    float* out = (float*)d_out;

    prep_emb_kernel<<<(3*16*CH3 + 255)/256, 256>>>();
    prep_ct_kernel<<<(Hc*Nst + 255)/256, 256>>>(log_dt, A_re, A_im, C_re, C_im);
    prep_wt_kernel<<<(Hc*OUTc/4 + 255)/256, 256>>>(W);
    v_kernel<<<(BSz*Hc*Lt/4 + 255)/256, 256>>>(x);
    ssmA_kernel<<<BSz*Hc*NCH/4, 128>>>();
    ssmB_kernel<<<BSz*Hc, 32>>>();
    ssmC_kernel<<<BSz*Hc*NCH/4, 128>>>(D);
    gemm_kernel<<<dim3(Lt/128, OUTc/64, BSz), 128>>>(bias, out);
}

// round 8
// speedup vs baseline: 1.7389x; 1.0836x over previous
#include <cuda_runtime.h>
#include <math.h>
#include <stdint.h>

#define Hc   1024
#define Nst  64
#define Lt   4096
#define OUTc 512
#define BSz  2
#define CH3  342   // per-axis posenc channels
#define Tc   256   // chunk length
#define NCH  16    // Lt / Tc

typedef unsigned long long u64;

// ---------------- f32x2 packed math (sm_103a FFMA2 path) ----------------
__device__ __forceinline__ u64 f2fma(u64 a, u64 b, u64 c) {
    u64 d; asm("fma.rn.f32x2 %0,%1,%2,%3;" : "=l"(d) : "l"(a), "l"(b), "l"(c)); return d;
}
__device__ __forceinline__ u64 f2mul(u64 a, u64 b) {
    u64 d; asm("mul.rn.f32x2 %0,%1,%2;" : "=l"(d) : "l"(a), "l"(b)); return d;
}
__device__ __forceinline__ u64 f2add(u64 a, u64 b) {
    u64 d; asm("add.rn.f32x2 %0,%1,%2;" : "=l"(d) : "l"(a), "l"(b)); return d;
}
__device__ __forceinline__ u64 f2pack(float lo, float hi) {
    u64 d; asm("mov.b64 %0,{%1,%2};" : "=l"(d) : "f"(lo), "f"(hi)); return d;
}
__device__ __forceinline__ u64 f2dup(float v) {
    u64 d; asm("mov.b64 %0,{%1,%1};" : "=l"(d) : "f"(v)); return d;
}
__device__ __forceinline__ float2 f2unpack(u64 v) {
    float2 r; asm("mov.b64 {%0,%1},%2;" : "=f"(r.x), "=f"(r.y) : "l"(v)); return r;
}
__device__ __forceinline__ float tf32rna(float v) {
    uint32_t u; asm("cvt.rna.tf32.f32 %0, %1;" : "=r"(u) : "f"(v));
    return __uint_as_float(u);
}

// ---------------- scratch ----------------
__device__ float g_v [BSz*Hc*Lt];     // v = x + pe, layout (b, c, l)
__device__ float g_yT[BSz*Hc*Lt];     // gelu(conv + D*v), tf32-rounded, (b, c, l)
__device__ float g_Wt[Hc*OUTc];       // W pre-rounded to tf32
__device__ float g_wre[Hc*Nst],  g_wim[Hc*Nst];
__device__ float g_w2re[Hc*Nst], g_w2im[Hc*Nst];   // w^2
__device__ float g_wTre[Hc*Nst], g_wTim[Hc*Nst];   // w^Tc
__device__ float g_ctre[Hc*Nst], g_ctim[Hc*Nst];
__device__ float g_emb[3*16*CH3];     // [axis][pos][k]
__device__ u64 g_csr[BSz*Hc*NCH*32], g_csi[BSz*Hc*NCH*32];  // chunk contributions
__device__ u64 g_s0r[BSz*Hc*NCH*32], g_s0i[BSz*Hc*NCH*32];  // chunk start states

// ---------------- posenc tables ----------------
__global__ void prep_emb_kernel() {
    int idx = blockIdx.x * blockDim.x + threadIdx.x;
    if (idx >= 3*16*CH3) return;
    int k   = idx % CH3;
    int pos = (idx / CH3) % 16;
    int i   = k >> 1;
    float freq = expf(-logf(10000.0f) * (float)(2*i) / (float)CH3);
    float arg  = (float)pos * freq;
    g_emb[idx] = (k & 1) ? cosf(arg) : sinf(arg);
}

// ---------------- W -> tf32 (round-to-nearest) ----------------
__global__ void prep_wt_kernel(const float* __restrict__ W) {
    int i4 = blockIdx.x * blockDim.x + threadIdx.x;
    if (i4 >= Hc*OUTc/4) return;
    float4 w = ((const float4*)W)[i4];
    ((float4*)g_Wt)[i4] = make_float4(tf32rna(w.x), tf32rna(w.y), tf32rna(w.z), tf32rna(w.w));
}

// ---------------- discretize (double precision for w^2 / w^Tc accuracy) ----------------
__global__ void prep_ct_kernel(const float* __restrict__ log_dt,
                               const float* __restrict__ Are, const float* __restrict__ Aim,
                               const float* __restrict__ Cre, const float* __restrict__ Cim) {
    int idx = blockIdx.x * blockDim.x + threadIdx.x;
    if (idx >= Hc*Nst) return;
    int c = idx >> 6;
    double dt  = exp((double)log_dt[c]);
    double ar  = (double)Are[idx], ai = (double)Aim[idx];
    double dar = dt*ar, dai = dt*ai;
    double er  = exp(dar);
    double wr = er*cos(dai), wi = er*sin(dai);
    g_wre[idx] = (float)wr; g_wim[idx] = (float)wi;
    double er2 = exp(2.0*dar);
    g_w2re[idx] = (float)(er2*cos(2.0*dai)); g_w2im[idx] = (float)(er2*sin(2.0*dai));
    double erT = exp((double)Tc * dar);
    g_wTre[idx] = (float)(erT*cos((double)Tc*dai)); g_wTim[idx] = (float)(erT*sin((double)Tc*dai));
    double nr = wr - 1.0, ni = wi;
    double inv = 1.0 / (ar*ar + ai*ai);
    double qr = (nr*ar + ni*ai) * inv;
    double qi = (ni*ar - nr*ai) * inv;
    double cr = (double)Cre[idx], ci = (double)Cim[idx];
    g_ctre[idx] = (float)(2.0*(cr*qr - ci*qi));
    g_ctim[idx] = (float)(2.0*(cr*qi + ci*qr));
}

// ---------------- v = x + posenc ----------------
__global__ void v_kernel(const float* __restrict__ x) {
    int i4 = blockIdx.x * blockDim.x + threadIdx.x;
    if (i4 >= BSz*Hc*Lt/4) return;
    int l4 = i4 & (Lt/4 - 1);
    int c  = (i4 >> 10) & (Hc - 1);
    int l  = l4 << 2;
    int lw = l & 15, lh = (l >> 4) & 15, lf = l >> 8;
    float4 xv = ((const float4*)x)[i4];
    float4 pv;
    if (c < CH3) {
        float e = g_emb[lf*CH3 + c];
        pv = make_float4(e, e, e, e);
    } else if (c < 2*CH3) {
        float e = g_emb[(16 + lh)*CH3 + (c - CH3)];
        pv = make_float4(e, e, e, e);
    } else {
        int k = c - 2*CH3;
        const float* ez = g_emb + 32*CH3 + k;
        pv = make_float4(ez[(lw+0)*CH3], ez[(lw+1)*CH3], ez[(lw+2)*CH3], ez[(lw+3)*CH3]);
    }
    ((float4*)g_v)[i4] = make_float4(xv.x+pv.x, xv.y+pv.y, xv.z+pv.z, xv.w+pv.w);
}

// ---------------- pass A: per-chunk recurrence from zero -> B_k (decim-by-2) ----------------
// 4 warps per block, one chunk per warp
__global__ __launch_bounds__(128) void ssmA_kernel() {
    int gid  = blockIdx.x * 4 + (threadIdx.x >> 5);   // (b*Hc+c)*NCH + k
    int lane = threadIdx.x & 31;
    int wid  = gid >> 4, k = gid & (NCH - 1);
    int c    = wid & (Hc - 1);
    int n0   = (c << 6) + lane;

    u64 Wr   = f2pack( g_wre[n0],   g_wre[n0+32]);
    u64 Wi   = f2pack( g_wim[n0],   g_wim[n0+32]);
    u64 W2r  = f2pack( g_w2re[n0],  g_w2re[n0+32]);
    u64 W2i  = f2pack( g_w2im[n0],  g_w2im[n0+32]);
    u64 W2in = f2pack(-g_w2im[n0], -g_w2im[n0+32]);

    const float4* vp = (const float4*)(g_v + (size_t)wid * Lt + k * Tc);
    u64 Sr = 0ull, Si = 0ull;

    for (int it = 0; it < Tc/8; ++it) {
        float4 a = vp[it*2], b = vp[it*2 + 1];
        #pragma unroll
        for (int g = 0; g < 4; ++g) {
            float v0 = (g==0)?a.x:(g==1)?a.z:(g==2)?b.x:b.z;
            float v1 = (g==0)?a.y:(g==1)?a.w:(g==2)?b.y:b.w;
            u64 v02 = f2dup(v0), v12 = f2dup(v1);
            // two steps: s = w2*s + (w*v0 + v1)
            u64 ir  = f2fma(Wr, v02, v12);
            u64 ii  = f2mul(Wi, v02);
            u64 tr  = f2fma(W2in, Si, ir);
            u64 nSr = f2fma(W2r,  Sr, tr);
            u64 ti  = f2fma(W2r,  Si, ii);
            Si      = f2fma(W2i,  Sr, ti);
            Sr      = nSr;
        }
    }
    g_csr[gid*32 + lane] = Sr;
    g_csi[gid*32 + lane] = Si;
}

// ---------------- pass B: scan chunk-start states ----------------
__global__ __launch_bounds__(32) void ssmB_kernel() {
    int wid  = blockIdx.x;               // b*Hc + c
    int lane = threadIdx.x;
    int c    = wid & (Hc - 1);
    int n0   = (c << 6) + lane;

    u64 WTr  = f2pack( g_wTre[n0],  g_wTre[n0+32]);
    u64 WTi  = f2pack( g_wTim[n0],  g_wTim[n0+32]);
    u64 WTin = f2pack(-g_wTim[n0], -g_wTim[n0+32]);

    u64 sr = 0ull, si = 0ull;
    #pragma unroll
    for (int k = 0; k < NCH; ++k) {
        int idx = (wid*NCH + k)*32 + lane;
        g_s0r[idx] = sr; g_s0i[idx] = si;
        u64 br = g_csr[idx], bi = g_csi[idx];
        u64 t  = f2fma(WTin, si, br);
        u64 u  = f2fma(WTr,  si, bi);
        u64 ns = f2fma(WTr,  sr, t);
        si     = f2fma(WTi,  sr, u);
        sr     = ns;
    }
}

// ---------------- pass C: two chunks per warp, interleaved ----------------
#define RP2 36   // words per reduce row (32 floats + 4 pad)

__global__ __launch_bounds__(128) void ssmC_kernel(const float* __restrict__ D) {
    __shared__ float ps[4][64*RP2];      // 36 KB
    int wrp  = threadIdx.x >> 5;
    int u    = blockIdx.x * 4 + wrp;     // (b*Hc+c)*(NCH/2) + p
    int lane = threadIdx.x & 31;
    int wid  = u >> 3, p = u & 7;
    int c    = wid & (Hc - 1);
    int n0   = (c << 6) + lane;
    int k0   = p << 1;                   // chunks k0, k0+1

    u64 Wr  = f2pack( g_wre[n0],   g_wre[n0+32]);
    u64 Wi  = f2pack( g_wim[n0],   g_wim[n0+32]);
    u64 Win = f2pack(-g_wim[n0],  -g_wim[n0+32]);
    u64 Cr  = f2pack( g_ctre[n0],  g_ctre[n0+32]);
    u64 Cin = f2pack(-g_ctim[n0], -g_ctim[n0+32]);
    float dc = D[c];

    const float* vbase = g_v + (size_t)wid * Lt + k0 * Tc;
    const float4* vpA  = (const float4*)vbase;
    const float4* vpB  = (const float4*)(vbase + Tc);
    float* ypA = g_yT + (size_t)wid * Lt + k0 * Tc;
    float* ypB = ypA + Tc;
    float* myps = ps[wrp];

    int sidx = (wid*NCH + k0)*32 + lane;
    u64 SrA = g_s0r[sidx],      SiA = g_s0i[sidx];
    u64 SrB = g_s0r[sidx + 32], SiB = g_s0i[sidx + 32];

    for (int base = 0; base < Tc; base += 32) {
        #pragma unroll
        for (int h = 0; h < 8; ++h) {
            float4 a = vpA[(base >> 2) + h];
            float4 b = vpB[(base >> 2) + h];
            #pragma unroll
            for (int j = 0; j < 4; ++j) {
                float vAf = (j==0)?a.x:(j==1)?a.y:(j==2)?a.z:a.w;
                float vBf = (j==0)?b.x:(j==1)?b.y:(j==2)?b.z:b.w;
                int row = h*4 + j;
                {   u64 vv = f2dup(vAf);
                    u64 t = f2fma(Win, SiA, vv); u64 uu = f2mul(Wr, SiA);
                    u64 n = f2fma(Wr, SrA, t); SiA = f2fma(Wi, SrA, uu); SrA = n;
                    float2 pf = f2unpack(f2fma(Cin, SiA, f2mul(Cr, SrA)));
                    myps[row*RP2 + lane] = pf.x + pf.y; }
                {   u64 vv = f2dup(vBf);
                    u64 t = f2fma(Win, SiB, vv); u64 uu = f2mul(Wr, SiB);
                    u64 n = f2fma(Wr, SrB, t); SiB = f2fma(Wi, SrB, uu); SrB = n;
                    float2 pf = f2unpack(f2fma(Cin, SiB, f2mul(Cr, SrB)));
                    myps[(row + 32)*RP2 + lane] = pf.x + pf.y; }
            }
        }
        __syncwarp();
        // lane t reduces row t (chunk A, step base+t) and row t+32 (chunk B)
        const ulonglong2* rowA = (const ulonglong2*)&myps[lane * RP2];
        const ulonglong2* rowB = (const ulonglong2*)&myps[(lane + 32) * RP2];
        u64 a0 = 0ull, a1 = 0ull, b0 = 0ull, b1 = 0ull;
        #pragma unroll
        for (int q = 0; q < 8; ++q) {
            ulonglong2 ra = rowA[q], rb = rowB[q];
            a0 = f2add(a0, ra.x); a1 = f2add(a1, ra.y);
            b0 = f2add(b0, rb.x); b1 = f2add(b1, rb.y);
        }
        float2 sfA = f2unpack(f2add(a0, a1));
        float2 sfB = f2unpack(f2add(b0, b1));
        float vA = vbase[base + lane];
        float vB = vbase[Tc + base + lane];
        float sA = sfA.x + sfA.y + dc * vA;
        float sB = sfB.x + sfB.y + dc * vB;
        float g2A = 1.5957691216057308f * fmaf(0.044715f * sA, sA * sA, sA);
        float g2B = 1.5957691216057308f * fmaf(0.044715f * sB, sB * sB, sB);
        float eA = __expf(g2A), eB = __expf(g2B);
        float thA = 1.0f - __fdividef(2.0f, eA + 1.0f);
        float thB = 1.0f - __fdividef(2.0f, eB + 1.0f);
        ypA[base + lane] = tf32rna(0.5f * sA * (1.0f + thA));
        ypB[base + lane] = tf32rna(0.5f * sB * (1.0f + thB));
        __syncwarp();
    }
}

// ---------------- tf32 tensor-core GEMM ----------------
// out[b,o,l] = sum_k Wt[k,o] * yT[b,k,l] + bias[o]
// tile: 128(o=M) x 128(l=N), BK=16, 256 threads = 8 warps (4M x 2N), warp tile 32x64
__global__ __launch_bounds__(256) void gemm_kernel(const float* __restrict__ bias,
                                                   float* __restrict__ out) {
    __shared__ float Ws[2][16][132];    // [k][o]
    __shared__ float Ys[2][16][132];    // [k][l]
    int b  = blockIdx.z;
    int oo = blockIdx.y << 7;
    int ll = blockIdx.x << 7;
    int t  = threadIdx.x;
    int lane = t & 31, wid = t >> 5;
    int om = (wid & 3) << 5;     // 0,32,64,96
    int on = (wid >> 2) << 6;    // 0,64
    int gID = lane >> 2, tig = lane & 3;

    int lr = t >> 4;                 // 0..15
    int lc = (t & 15) << 2;          // 0..60
    const float* Wp = g_Wt + (size_t)lr * OUTc + oo + lc;
    const float* Yp = g_yT + ((size_t)b * Hc + lr) * Lt + ll + lc;

    float4 wv0 = *(const float4*)Wp;
    float4 wv1 = *(const float4*)(Wp + 64);
    float4 yv0 = *(const float4*)Yp;
    float4 yv1 = *(const float4*)(Yp + 64);

    float acc[2][8][4];
    #pragma unroll
    for (int mt = 0; mt < 2; ++mt)
        #pragma unroll
        for (int nt = 0; nt < 8; ++nt)
            #pragma unroll
            for (int r = 0; r < 4; ++r) acc[mt][nt][r] = 0.f;

    int buf = 0;
    for (int s = 0; s < Hc/16; ++s) {
        *(float4*)&Ws[buf][lr][lc]      = wv0;
        *(float4*)&Ws[buf][lr][lc + 64] = wv1;
        *(float4*)&Ys[buf][lr][lc]      = yv0;
        *(float4*)&Ys[buf][lr][lc + 64] = yv1;
        __syncthreads();
        if (s + 1 < Hc/16) {
            size_t ko = (size_t)(s + 1) * 16;
            wv0 = *(const float4*)(Wp + ko * OUTc);
            wv1 = *(const float4*)(Wp + ko * OUTc + 64);
            yv0 = *(const float4*)(Yp + ko * Lt);
            yv1 = *(const float4*)(Yp + ko * Lt + 64);
        }
        #pragma unroll
        for (int k8 = 0; k8 < 16; k8 += 8) {
            uint32_t a[2][4];
            #pragma unroll
            for (int mt = 0; mt < 2; ++mt) {
                int r0 = om + (mt << 4) + gID;
                a[mt][0] = __float_as_uint(Ws[buf][k8 + tig    ][r0]);
                a[mt][1] = __float_as_uint(Ws[buf][k8 + tig    ][r0 + 8]);
                a[mt][2] = __float_as_uint(Ws[buf][k8 + tig + 4][r0]);
                a[mt][3] = __float_as_uint(Ws[buf][k8 + tig + 4][r0 + 8]);
            }
            uint32_t bf[8][2];
            #pragma unroll
            for (int nt = 0; nt < 8; ++nt) {
                int cn = on + (nt << 3) + gID;
                bf[nt][0] = __float_as_uint(Ys[buf][k8 + tig    ][cn]);
                bf[nt][1] = __float_as_uint(Ys[buf][k8 + tig + 4][cn]);
            }
            #pragma unroll
            for (int mt = 0; mt < 2; ++mt)
                #pragma unroll
                for (int nt = 0; nt < 8; ++nt) {
                    asm("mma.sync.aligned.m16n8k8.row.col.f32.tf32.tf32.f32 "
                        "{%0,%1,%2,%3},{%4,%5,%6,%7},{%8,%9},{%0,%1,%2,%3};"
                        : "+f"(acc[mt][nt][0]), "+f"(acc[mt][nt][1]),
                          "+f"(acc[mt][nt][2]), "+f"(acc[mt][nt][3])
                        : "r"(a[mt][0]), "r"(a[mt][1]), "r"(a[mt][2]), "r"(a[mt][3]),
                          "r"(bf[nt][0]), "r"(bf[nt][1]));
                }
        }
        buf ^= 1;
    }

    #pragma unroll
    for (int mt = 0; mt < 2; ++mt) {
        int o0 = oo + om + (mt << 4) + gID;
        float b0 = __ldg(&bias[o0]);
        float b8 = __ldg(&bias[o0 + 8]);
        float* r0p = out + ((size_t)b * OUTc + o0)     * Lt + ll + on + (tig << 1);
        float* r8p = out + ((size_t)b * OUTc + o0 + 8) * Lt + ll + on + (tig << 1);
        #pragma unroll
        for (int nt = 0; nt < 8; ++nt) {
            *(float2*)(r0p + (nt << 3)) = make_float2(acc[mt][nt][0] + b0, acc[mt][nt][1] + b0);
            *(float2*)(r8p + (nt << 3)) = make_float2(acc[mt][nt][2] + b8, acc[mt][nt][3] + b8);
        }
    }
}

// ---------------- launch ----------------
extern "C" void kernel_launch(void* const* d_in, const int* in_sizes, int n_in,
                              void* d_out, int out_size) {
    const float* x      = (const float*)d_in[0];
    const float* log_dt = (const float*)d_in[1];
    const float* A_re   = (const float*)d_in[2];
    const float* A_im   = (const float*)d_in[3];
    const float* C_re   = (const float*)d_in[4];
    const float* C_im   = (const float*)d_in[5];
    const float* D      = (const float*)d_in[6];
    const float* W      = (const float*)d_in[7];
    const float* bias   = (const float*)d_in[8];
    float* out = (float*)d_out;

    prep_emb_kernel<<<(3*16*CH3 + 255)/256, 256>>>();
    prep_ct_kernel<<<(Hc*Nst + 255)/256, 256>>>(log_dt, A_re, A_im, C_re, C_im);
    prep_wt_kernel<<<(Hc*OUTc/4 + 255)/256, 256>>>(W);
    v_kernel<<<(BSz*Hc*Lt/4 + 255)/256, 256>>>(x);
    ssmA_kernel<<<BSz*Hc*NCH/4, 128>>>();
    ssmB_kernel<<<BSz*Hc, 32>>>();
    ssmC_kernel<<<BSz*Hc*NCH/8, 128>>>(D);
    gemm_kernel<<<dim3(Lt/128, OUTc/128, BSz), 256>>>(bias, out);
}